// round 1
// baseline (speedup 1.0000x reference)
#include <cuda_runtime.h>
#include <math_constants.h>

#define EMBED  512
#define HEADS  2
#define HDIM   256
#define NTXT   4096   // 128*32 text tokens
#define NVID   768    // 64*12 video tokens
#define FRAMES 12
#define VIDS   64
#define TTOK   4096

// ---- scratch (device globals; no runtime allocation) ----
__device__ float g_tln [NTXT*EMBED];
__device__ float g_vln [NVID*EMBED];
__device__ float g_q   [NTXT*EMBED];
__device__ float g_k   [NVID*EMBED];
__device__ float g_v   [NVID*EMBED];
__device__ float g_s   [HEADS*(size_t)NVID*TTOK];   // logits / probs
__device__ float g_attn[NTXT*EMBED];
__device__ float g_o   [NTXT*EMBED];
__device__ float g_lin [NTXT*EMBED];

// ============================================================
// LayerNorm over rows of 512. Optional second addend (x2) for
// the final residual + LN3. blockDim = 256, one block per row.
// ============================================================
__global__ __launch_bounds__(256) void ln_kernel(
    const float* __restrict__ x, const float* __restrict__ x2,
    float* __restrict__ y,
    const float* __restrict__ g, const float* __restrict__ b)
{
    int row = blockIdx.x;
    const float* xr  = x + (size_t)row * EMBED;
    const float* xr2 = x2 ? (x2 + (size_t)row * EMBED) : nullptr;

    float vals[2];
    float s = 0.f, s2 = 0.f;
#pragma unroll
    for (int it = 0; it < 2; it++) {
        int i = threadIdx.x + it * 256;
        float v = xr[i];
        if (xr2) v += xr2[i];
        vals[it] = v;
        s += v; s2 += v * v;
    }
#pragma unroll
    for (int o = 16; o; o >>= 1) {
        s  += __shfl_xor_sync(0xffffffffu, s,  o);
        s2 += __shfl_xor_sync(0xffffffffu, s2, o);
    }
    __shared__ float rs[8], rs2[8];
    int w = threadIdx.x >> 5;
    if ((threadIdx.x & 31) == 0) { rs[w] = s; rs2[w] = s2; }
    __syncthreads();
    if (threadIdx.x < 32) {
        float a  = threadIdx.x < 8 ? rs [threadIdx.x] : 0.f;
        float a2 = threadIdx.x < 8 ? rs2[threadIdx.x] : 0.f;
#pragma unroll
        for (int o = 4; o; o >>= 1) {
            a  += __shfl_xor_sync(0xffffffffu, a,  o);
            a2 += __shfl_xor_sync(0xffffffffu, a2, o);
        }
        if (threadIdx.x == 0) { rs[0] = a; rs2[0] = a2; }
    }
    __syncthreads();
    float mu  = rs[0]  * (1.f / EMBED);
    float var = rs2[0] * (1.f / EMBED) - mu * mu;
    float inv = rsqrtf(var + 1e-5f);
#pragma unroll
    for (int it = 0; it < 2; it++) {
        int i = threadIdx.x + it * 256;
        y[(size_t)row * EMBED + i] = (vals[it] - mu) * inv * g[i] + b[i];
    }
}

// ============================================================
// NT GEMM: C[m, offC+n] = alpha * sum_k A[m, offA+k] * B[n, offB+k] (+ bias[n])
// Both operands K-contiguous. 64x64x16 tiles, 256 threads, 4x4 microtile.
// Requires M%64==0, N%64==0, K%16==0.
// ============================================================
__global__ __launch_bounds__(256) void gemm_nt(
    const float* __restrict__ A, int lda, int offA,
    const float* __restrict__ B, int ldb, int offB,
    const float* __restrict__ bias,
    float* __restrict__ C, int ldc, int offC,
    int K, float alpha)
{
    __shared__ float As[16][68];
    __shared__ float Bs[16][68];
    int tid = threadIdx.x;
    int tx = tid & 15, ty = tid >> 4;
    int m0 = blockIdx.y * 64, n0 = blockIdx.x * 64;
    int lr = tid >> 2;            // 0..63  tile row
    int lc = (tid & 3) << 2;      // 0,4,8,12 k-offset

    const float* Ap = A + (size_t)(m0 + lr) * lda + offA + lc;
    const float* Bp = B + (size_t)(n0 + lr) * ldb + offB + lc;

    float acc[4][4] = {};
    for (int k0 = 0; k0 < K; k0 += 16) {
        float4 av = *(const float4*)(Ap + k0);
        float4 bv = *(const float4*)(Bp + k0);
        As[lc+0][lr] = av.x; As[lc+1][lr] = av.y; As[lc+2][lr] = av.z; As[lc+3][lr] = av.w;
        Bs[lc+0][lr] = bv.x; Bs[lc+1][lr] = bv.y; Bs[lc+2][lr] = bv.z; Bs[lc+3][lr] = bv.w;
        __syncthreads();
#pragma unroll
        for (int kk = 0; kk < 16; kk++) {
            float4 a = *(const float4*)&As[kk][ty << 2];
            float4 b = *(const float4*)&Bs[kk][tx << 2];
            float aa[4] = {a.x, a.y, a.z, a.w};
            float bb[4] = {b.x, b.y, b.z, b.w};
#pragma unroll
            for (int i = 0; i < 4; i++)
#pragma unroll
                for (int j = 0; j < 4; j++)
                    acc[i][j] += aa[i] * bb[j];
        }
        __syncthreads();
    }
#pragma unroll
    for (int i = 0; i < 4; i++) {
        int m = m0 + (ty << 2) + i;
#pragma unroll
        for (int j = 0; j < 4; j++) {
            int n = n0 + (tx << 2) + j;
            float r = alpha * acc[i][j];
            if (bias) r += bias[n];
            C[(size_t)m * ldc + offC + n] = r;
        }
    }
}

// ============================================================
// TN GEMM: C[m, offC+n] = alpha * sum_k A[k, m] * B[k, offB+n]
// (A is [K, M] row-major, B is [K, N] row-major)
// Used for attn = (1/64) * P^T * V_h. Same tiling.
// ============================================================
__global__ __launch_bounds__(256) void gemm_tn(
    const float* __restrict__ A, int lda,
    const float* __restrict__ B, int ldb, int offB,
    float* __restrict__ C, int ldc, int offC,
    int K, float alpha)
{
    __shared__ float As[16][68];
    __shared__ float Bs[16][68];
    int tid = threadIdx.x;
    int tx = tid & 15, ty = tid >> 4;
    int m0 = blockIdx.y * 64, n0 = blockIdx.x * 64;
    int kr = tid >> 4;            // 0..15
    int cc = (tid & 15) << 2;     // 0..60

    float acc[4][4] = {};
    for (int k0 = 0; k0 < K; k0 += 16) {
        float4 av = *(const float4*)(A + (size_t)(k0 + kr) * lda + m0 + cc);
        float4 bv = *(const float4*)(B + (size_t)(k0 + kr) * ldb + offB + n0 + cc);
        *(float4*)&As[kr][cc] = av;
        *(float4*)&Bs[kr][cc] = bv;
        __syncthreads();
#pragma unroll
        for (int kk = 0; kk < 16; kk++) {
            float4 a = *(const float4*)&As[kk][ty << 2];
            float4 b = *(const float4*)&Bs[kk][tx << 2];
            float aa[4] = {a.x, a.y, a.z, a.w};
            float bb[4] = {b.x, b.y, b.z, b.w};
#pragma unroll
            for (int i = 0; i < 4; i++)
#pragma unroll
                for (int j = 0; j < 4; j++)
                    acc[i][j] += aa[i] * bb[j];
        }
        __syncthreads();
    }
#pragma unroll
    for (int i = 0; i < 4; i++) {
        int m = m0 + (ty << 2) + i;
#pragma unroll
        for (int j = 0; j < 4; j++) {
            int n = n0 + (tx << 2) + j;
            C[(size_t)m * ldc + offC + n] = alpha * acc[i][j];
        }
    }
}

// ============================================================
// Softmax over the 12 frames of each video, per (head, video, text-col).
// S layout: [HEADS][NVID rows = a*12+f][TTOK cols]
// ============================================================
__global__ __launch_bounds__(256) void softmax_frames(float* __restrict__ S)
{
    int idx = blockIdx.x * 256 + threadIdx.x;   // (h*VIDS + a)*TTOK + t
    if (idx >= HEADS * VIDS * TTOK) return;
    int t  = idx & (TTOK - 1);
    int ha = idx >> 12;          // TTOK = 2^12
    int a  = ha & (VIDS - 1);
    int h  = ha >> 6;            // VIDS = 2^6
    float* base = S + ((size_t)h * NVID + (size_t)a * FRAMES) * TTOK + t;

    float vals[FRAMES];
    float m = -CUDART_INF_F;
#pragma unroll
    for (int f = 0; f < FRAMES; f++) {
        vals[f] = base[(size_t)f * TTOK];
        m = fmaxf(m, vals[f]);
    }
    float s = 0.f;
#pragma unroll
    for (int f = 0; f < FRAMES; f++) {
        vals[f] = __expf(vals[f] - m);
        s += vals[f];
    }
    float inv = 1.f / s;
#pragma unroll
    for (int f = 0; f < FRAMES; f++)
        base[(size_t)f * TTOK] = vals[f] * inv;
}

// ============================================================
extern "C" void kernel_launch(void* const* d_in, const int* in_sizes, int n_in,
                              void* d_out, int out_size)
{
    const float* text  = (const float*)d_in[0];
    const float* video = (const float*)d_in[1];
    const float* ln1_g = (const float*)d_in[2];
    const float* ln1_b = (const float*)d_in[3];
    const float* Wq    = (const float*)d_in[4];
    const float* bq    = (const float*)d_in[5];
    const float* Wk    = (const float*)d_in[6];
    const float* bk    = (const float*)d_in[7];
    const float* Wv    = (const float*)d_in[8];
    const float* bv    = (const float*)d_in[9];
    const float* Wo    = (const float*)d_in[10];
    const float* bo    = (const float*)d_in[11];
    const float* Wl    = (const float*)d_in[12];
    const float* bl    = (const float*)d_in[13];
    const float* ln2_g = (const float*)d_in[14];
    const float* ln2_b = (const float*)d_in[15];
    const float* ln3_g = (const float*)d_in[16];
    const float* ln3_b = (const float*)d_in[17];
    float* out = (float*)d_out;

    float *tln, *vln, *q, *k, *v, *s, *attn, *o, *lin;
    cudaGetSymbolAddress((void**)&tln,  g_tln);
    cudaGetSymbolAddress((void**)&vln,  g_vln);
    cudaGetSymbolAddress((void**)&q,    g_q);
    cudaGetSymbolAddress((void**)&k,    g_k);
    cudaGetSymbolAddress((void**)&v,    g_v);
    cudaGetSymbolAddress((void**)&s,    g_s);
    cudaGetSymbolAddress((void**)&attn, g_attn);
    cudaGetSymbolAddress((void**)&o,    g_o);
    cudaGetSymbolAddress((void**)&lin,  g_lin);

    // 1) shared LN1 on both modalities
    ln_kernel<<<NTXT, 256>>>(text,  nullptr, tln, ln1_g, ln1_b);
    ln_kernel<<<NVID, 256>>>(video, nullptr, vln, ln1_g, ln1_b);

    // 2) Q / K / V projections (NT: x @ W^T + b)
    gemm_nt<<<dim3(8, 64), 256>>>(tln, EMBED, 0, Wq, EMBED, 0, bq, q, EMBED, 0, EMBED, 1.f);
    gemm_nt<<<dim3(8, 12), 256>>>(vln, EMBED, 0, Wk, EMBED, 0, bk, k, EMBED, 0, EMBED, 1.f);
    gemm_nt<<<dim3(8, 12), 256>>>(vln, EMBED, 0, Wv, EMBED, 0, bv, v, EMBED, 0, EMBED, 1.f);

    // 3) logits per head: S_h[768, 4096] = (1/16) * K_h @ Q_h^T
    const float scl = 1.f / 16.f;  // 1/sqrt(256)
    for (int h = 0; h < HEADS; h++)
        gemm_nt<<<dim3(64, 12), 256>>>(k, EMBED, h * HDIM, q, EMBED, h * HDIM,
                                       nullptr, s + (size_t)h * NVID * TTOK, TTOK, 0,
                                       HDIM, scl);

    // 4) softmax over 12 frames within each video block, per column
    softmax_frames<<<(HEADS * VIDS * TTOK) / 256, 256>>>(s);

    // 5) attention output + mean over videos, fused into one TN GEMM per head:
    //    attn[m, h*256+d] = (1/64) * sum_r P_h[r, m] * V[r, h*256+d]
    for (int h = 0; h < HEADS; h++)
        gemm_tn<<<dim3(4, 64), 256>>>(s + (size_t)h * NVID * TTOK, TTOK,
                                      v, EMBED, h * HDIM,
                                      attn, EMBED, h * HDIM, NVID, 1.f / 64.f);

    // 6) output projection + LN2
    gemm_nt<<<dim3(8, 64), 256>>>(attn, EMBED, 0, Wo, EMBED, 0, bo, tln, EMBED, 0, EMBED, 1.f);
    ln_kernel<<<NTXT, 256>>>(tln, nullptr, o, ln2_g, ln2_b);

    // 7) linear + residual + LN3
    gemm_nt<<<dim3(8, 64), 256>>>(o, EMBED, 0, Wl, EMBED, 0, bl, lin, EMBED, 0, EMBED, 1.f);
    ln_kernel<<<NTXT, 256>>>(o, lin, out, ln3_g, ln3_b);
}

// round 5
// speedup vs baseline: 1.0603x; 1.0603x over previous
#include <cuda_runtime.h>
#include <math_constants.h>

typedef unsigned long long u64;

#define EMBED  512
#define HEADS  2
#define HDIM   256
#define NTXT   4096   // 128*32 text tokens
#define NVID   768    // 64*12 video tokens
#define FRAMES 12
#define VIDS   64
#define TTOK   4096

#define BM 128
#define BN 128
#define BK 16

// ---- scratch (device globals; no runtime allocation) ----
__device__ float g_tln [NTXT*EMBED];
__device__ float g_vln [NVID*EMBED];
__device__ float g_q   [NTXT*EMBED];
__device__ float g_k   [NVID*EMBED];
__device__ float g_v   [NVID*EMBED];
__device__ float g_s   [HEADS*(size_t)NVID*TTOK];   // logits / probs
__device__ float g_attn[NTXT*EMBED];
__device__ float g_o   [NTXT*EMBED];
__device__ float g_lin [NTXT*EMBED];

// packed dual-FMA: d = a*b + d elementwise on (lo,hi) fp32 pairs -> SASS FFMA2
__device__ __forceinline__ void ffma2(u64& d, u64 a, u64 b) {
    asm("fma.rn.f32x2 %0, %1, %2, %3;" : "=l"(d) : "l"(a), "l"(b), "l"(d));
}
__device__ __forceinline__ float2 unpack2(u64 x) {
    unsigned lo, hi;
    asm("mov.b64 {%0,%1}, %2;" : "=r"(lo), "=r"(hi) : "l"(x));
    return make_float2(__uint_as_float(lo), __uint_as_float(hi));
}

// ============================================================
// f32x2 GEMM core. 128x128x16 tiles, 256 threads, 8x8 microtile
// held as 8x4 packed accumulators.
//   TN=false : C[m,n] = alpha*sum_k A[m,k]*B[n,k] (+bias[n])   (both K-contig)
//   TN=true  : C[m,n] = alpha*sum_k A[k,m]*B[k,n]              (both MN-contig)
// A is staged in smem duplicated ((a,a) pairs) so the packed
// multiplier comes straight out of LDS.128 with no pack ops.
// Requires M%128==0, N%128==0, K%16==0.
// ============================================================
template<bool TN>
__device__ __forceinline__ void gemm_core(
    const float* __restrict__ A, int lda,
    const float* __restrict__ B, int ldb,
    const float* __restrict__ bias,
    float* __restrict__ C, int ldc,
    int K, float alpha, int m0, int n0)
{
    __shared__ float As[2][BK][2*BM];   // duplicated A (32 KB)
    __shared__ float Bs[2][BK][BN];     // 16 KB
    // total 48 KB static smem -> 1 block/SM

    const int tid = threadIdx.x;
    const int tx8 = (tid & 15) * 8;     // n within tile
    const int ty8 = (tid >> 4) * 8;     // m within tile

    // global-load mappings
    const int lm  = tid >> 2;           // NT: row (m or n), 0..63 (+64 second chunk)
    const int lk  = (tid & 3) * 4;      // NT: k offset 0,4,8,12
    const int tk  = tid >> 5;           // TN: k row 0..7 (+8 second chunk)
    const int tm4 = (tid & 31) * 4;     // TN: col offset 0..124

    float4 pa0, pa1, pb0, pb1;

    auto loadg = [&](int s) {
        if (!TN) {
            const float* Ag = A + (size_t)(m0 + lm) * lda + lk + s * BK;
            const float* Bg = B + (size_t)(n0 + lm) * ldb + lk + s * BK;
            pa0 = *(const float4*)Ag;
            pa1 = *(const float4*)(Ag + (size_t)64 * lda);
            pb0 = *(const float4*)Bg;
            pb1 = *(const float4*)(Bg + (size_t)64 * ldb);
        } else {
            const float* Ag = A + ((size_t)tk + (size_t)s * BK) * lda + m0 + tm4;
            const float* Bg = B + ((size_t)tk + (size_t)s * BK) * ldb + n0 + tm4;
            pa0 = *(const float4*)Ag;
            pa1 = *(const float4*)(Ag + (size_t)8 * lda);
            pb0 = *(const float4*)Bg;
            pb1 = *(const float4*)(Bg + (size_t)8 * ldb);
        }
    };
    auto stores = [&](int bb) {
        if (!TN) {
            float va0[4] = {pa0.x, pa0.y, pa0.z, pa0.w};
            float va1[4] = {pa1.x, pa1.y, pa1.z, pa1.w};
            float vb0[4] = {pb0.x, pb0.y, pb0.z, pb0.w};
            float vb1[4] = {pb1.x, pb1.y, pb1.z, pb1.w};
#pragma unroll
            for (int j = 0; j < 4; j++) {
                *(float2*)&As[bb][lk+j][2*lm]        = make_float2(va0[j], va0[j]);
                *(float2*)&As[bb][lk+j][2*(lm+64)]   = make_float2(va1[j], va1[j]);
                Bs[bb][lk+j][lm]      = vb0[j];
                Bs[bb][lk+j][lm+64]   = vb1[j];
            }
        } else {
            *(float4*)&As[bb][tk  ][2*tm4]   = make_float4(pa0.x, pa0.x, pa0.y, pa0.y);
            *(float4*)&As[bb][tk  ][2*tm4+4] = make_float4(pa0.z, pa0.z, pa0.w, pa0.w);
            *(float4*)&As[bb][tk+8][2*tm4]   = make_float4(pa1.x, pa1.x, pa1.y, pa1.y);
            *(float4*)&As[bb][tk+8][2*tm4+4] = make_float4(pa1.z, pa1.z, pa1.w, pa1.w);
            *(float4*)&Bs[bb][tk  ][tm4]     = pb0;
            *(float4*)&Bs[bb][tk+8][tm4]     = pb1;
        }
    };

    u64 acc[8][4];
#pragma unroll
    for (int i = 0; i < 8; i++)
#pragma unroll
        for (int j = 0; j < 4; j++) acc[i][j] = 0ull;

    const int S = K / BK;
    int buf = 0;
    loadg(0);
    stores(0);
    __syncthreads();

    for (int s = 0; s < S; s++) {
        if (s + 1 < S) loadg(s + 1);
#pragma unroll
        for (int kk = 0; kk < BK; kk++) {
            const float* Ar = &As[buf][kk][2*ty8];
            const float* Br = &Bs[buf][kk][tx8];
            ulonglong2 ap0 = *(const ulonglong2*)(Ar);
            ulonglong2 ap1 = *(const ulonglong2*)(Ar + 4);
            ulonglong2 ap2 = *(const ulonglong2*)(Ar + 8);
            ulonglong2 ap3 = *(const ulonglong2*)(Ar + 12);
            ulonglong2 bq0 = *(const ulonglong2*)(Br);
            ulonglong2 bq1 = *(const ulonglong2*)(Br + 4);
            u64 a[8] = {ap0.x, ap0.y, ap1.x, ap1.y, ap2.x, ap2.y, ap3.x, ap3.y};
            u64 b[4] = {bq0.x, bq0.y, bq1.x, bq1.y};
#pragma unroll
            for (int i = 0; i < 8; i++)
#pragma unroll
                for (int j = 0; j < 4; j++)
                    ffma2(acc[i][j], a[i], b[j]);
        }
        if (s + 1 < S) {
            stores(buf ^ 1);
            __syncthreads();
            buf ^= 1;
        }
    }

    // epilogue
    const float* biasp = bias ? bias + n0 + tx8 : nullptr;
#pragma unroll
    for (int i = 0; i < 8; i++) {
        float2 v0 = unpack2(acc[i][0]), v1 = unpack2(acc[i][1]);
        float2 v2 = unpack2(acc[i][2]), v3 = unpack2(acc[i][3]);
        float r[8] = {v0.x, v0.y, v1.x, v1.y, v2.x, v2.y, v3.x, v3.y};
        float* Cr = C + (size_t)(m0 + ty8 + i) * ldc + n0 + tx8;
#pragma unroll
        for (int jj = 0; jj < 8; jj++) {
            float val = r[jj] * alpha;
            if (biasp) val += biasp[jj];
            r[jj] = val;
        }
        *(float4*)Cr       = make_float4(r[0], r[1], r[2], r[3]);
        *(float4*)(Cr + 4) = make_float4(r[4], r[5], r[6], r[7]);
    }
}

// ---- kernel wrappers (grid.z = batched job / head) ----
__global__ __launch_bounds__(256, 1) void gemm_nt_kernel(
    const float* __restrict__ A, int lda, int zsA,
    const float* __restrict__ B, int ldb, int zsB,
    const float* __restrict__ bias,
    float* __restrict__ C, int ldc, size_t zsC,
    int K, float alpha)
{
    int z = blockIdx.z;
    gemm_core<false>(A + (size_t)z * zsA, lda, B + (size_t)z * zsB, ldb, bias,
                     C + (size_t)z * zsC, ldc, K, alpha,
                     blockIdx.y * BM, blockIdx.x * BN);
}

__global__ __launch_bounds__(256, 1) void gemm_tn_kernel(
    const float* __restrict__ A, int lda, size_t zsA,
    const float* __restrict__ B, int ldb, int zsB,
    float* __restrict__ C, int ldc, int zsC,
    int K, float alpha)
{
    int z = blockIdx.z;
    gemm_core<true>(A + (size_t)z * zsA, lda, B + (size_t)z * zsB, ldb, nullptr,
                    C + (size_t)z * zsC, ldc, K, alpha,
                    blockIdx.y * BM, blockIdx.x * BN);
}

// fused Q/K/V projections in one launch (z=0:Q, z=1:K, z=2:V)
__global__ __launch_bounds__(256, 1) void qkv_kernel(
    const float* __restrict__ tln, const float* __restrict__ vln,
    const float* __restrict__ Wq, const float* __restrict__ bq,
    const float* __restrict__ Wk, const float* __restrict__ bk,
    const float* __restrict__ Wv, const float* __restrict__ bv,
    float* __restrict__ q, float* __restrict__ k, float* __restrict__ v)
{
    int z = blockIdx.z;
    const float *A, *B, *bias; float* C;
    if (z == 0) { A = tln; B = Wq; bias = bq; C = q; }
    else {
        if (blockIdx.y >= NVID / BM) return;   // video has only 6 m-tiles
        A = vln;
        if (z == 1) { B = Wk; bias = bk; C = k; }
        else        { B = Wv; bias = bv; C = v; }
    }
    gemm_core<false>(A, EMBED, B, EMBED, bias, C, EMBED, EMBED, 1.f,
                     blockIdx.y * BM, blockIdx.x * BN);
}

// ============================================================
// LayerNorm over rows of 512 (+ optional residual addend x2)
// ============================================================
__global__ __launch_bounds__(256) void ln_kernel(
    const float* __restrict__ x, const float* __restrict__ x2,
    float* __restrict__ y,
    const float* __restrict__ g, const float* __restrict__ b)
{
    int row = blockIdx.x;
    const float* xr  = x + (size_t)row * EMBED;
    const float* xr2 = x2 ? (x2 + (size_t)row * EMBED) : nullptr;

    float vals[2];
    float s = 0.f, s2 = 0.f;
#pragma unroll
    for (int it = 0; it < 2; it++) {
        int i = threadIdx.x + it * 256;
        float v = xr[i];
        if (xr2) v += xr2[i];
        vals[it] = v;
        s += v; s2 += v * v;
    }
#pragma unroll
    for (int o = 16; o; o >>= 1) {
        s  += __shfl_xor_sync(0xffffffffu, s,  o);
        s2 += __shfl_xor_sync(0xffffffffu, s2, o);
    }
    __shared__ float rs[8], rs2[8];
    int w = threadIdx.x >> 5;
    if ((threadIdx.x & 31) == 0) { rs[w] = s; rs2[w] = s2; }
    __syncthreads();
    if (threadIdx.x < 32) {
        float a  = threadIdx.x < 8 ? rs [threadIdx.x] : 0.f;
        float a2 = threadIdx.x < 8 ? rs2[threadIdx.x] : 0.f;
#pragma unroll
        for (int o = 4; o; o >>= 1) {
            a  += __shfl_xor_sync(0xffffffffu, a,  o);
            a2 += __shfl_xor_sync(0xffffffffu, a2, o);
        }
        if (threadIdx.x == 0) { rs[0] = a; rs2[0] = a2; }
    }
    __syncthreads();
    float mu  = rs[0]  * (1.f / EMBED);
    float var = rs2[0] * (1.f / EMBED) - mu * mu;
    float inv = rsqrtf(var + 1e-5f);
#pragma unroll
    for (int it = 0; it < 2; it++) {
        int i = threadIdx.x + it * 256;
        y[(size_t)row * EMBED + i] = (vals[it] - mu) * inv * g[i] + b[i];
    }
}

// ============================================================
// Softmax over the 12 frames of each video per (head, video, col)
// ============================================================
__global__ __launch_bounds__(256) void softmax_frames(float* __restrict__ S)
{
    int idx = blockIdx.x * 256 + threadIdx.x;
    if (idx >= HEADS * VIDS * TTOK) return;
    int t  = idx & (TTOK - 1);
    int ha = idx >> 12;
    int a  = ha & (VIDS - 1);
    int h  = ha >> 6;
    float* base = S + ((size_t)h * NVID + (size_t)a * FRAMES) * TTOK + t;

    float vals[FRAMES];
    float m = -CUDART_INF_F;
#pragma unroll
    for (int f = 0; f < FRAMES; f++) {
        vals[f] = base[(size_t)f * TTOK];
        m = fmaxf(m, vals[f]);
    }
    float sum = 0.f;
#pragma unroll
    for (int f = 0; f < FRAMES; f++) {
        vals[f] = __expf(vals[f] - m);
        sum += vals[f];
    }
    float inv = 1.f / sum;
#pragma unroll
    for (int f = 0; f < FRAMES; f++)
        base[(size_t)f * TTOK] = vals[f] * inv;
}

// ============================================================
extern "C" void kernel_launch(void* const* d_in, const int* in_sizes, int n_in,
                              void* d_out, int out_size)
{
    const float* text  = (const float*)d_in[0];
    const float* video = (const float*)d_in[1];
    const float* ln1_g = (const float*)d_in[2];
    const float* ln1_b = (const float*)d_in[3];
    const float* Wq    = (const float*)d_in[4];
    const float* bq    = (const float*)d_in[5];
    const float* Wk    = (const float*)d_in[6];
    const float* bk    = (const float*)d_in[7];
    const float* Wv    = (const float*)d_in[8];
    const float* bv    = (const float*)d_in[9];
    const float* Wo    = (const float*)d_in[10];
    const float* bo    = (const float*)d_in[11];
    const float* Wl    = (const float*)d_in[12];
    const float* bl    = (const float*)d_in[13];
    const float* ln2_g = (const float*)d_in[14];
    const float* ln2_b = (const float*)d_in[15];
    const float* ln3_g = (const float*)d_in[16];
    const float* ln3_b = (const float*)d_in[17];
    float* out = (float*)d_out;

    float *tln, *vln, *q, *k, *v, *s, *attn, *o, *lin;
    cudaGetSymbolAddress((void**)&tln,  g_tln);
    cudaGetSymbolAddress((void**)&vln,  g_vln);
    cudaGetSymbolAddress((void**)&q,    g_q);
    cudaGetSymbolAddress((void**)&k,    g_k);
    cudaGetSymbolAddress((void**)&v,    g_v);
    cudaGetSymbolAddress((void**)&s,    g_s);
    cudaGetSymbolAddress((void**)&attn, g_attn);
    cudaGetSymbolAddress((void**)&o,    g_o);
    cudaGetSymbolAddress((void**)&lin,  g_lin);

    // 1) shared LN1 on both modalities
    ln_kernel<<<NTXT, 256>>>(text,  nullptr, tln, ln1_g, ln1_b);
    ln_kernel<<<NVID, 256>>>(video, nullptr, vln, ln1_g, ln1_b);

    // 2) fused Q/K/V projections (NT: x @ W^T + b), one launch
    qkv_kernel<<<dim3(EMBED/BN, NTXT/BM, 3), 256>>>(
        tln, vln, Wq, bq, Wk, bk, Wv, bv, q, k, v);

    // 3) logits, both heads in one launch: S_h[768,4096] = (1/16) K_h @ Q_h^T
    gemm_nt_kernel<<<dim3(TTOK/BN, NVID/BM, HEADS), 256>>>(
        k, EMBED, HDIM, q, EMBED, HDIM, nullptr,
        s, TTOK, (size_t)NVID * TTOK, HDIM, 1.f / 16.f);

    // 4) softmax over 12 frames per video per column
    softmax_frames<<<(HEADS * VIDS * TTOK) / 256, 256>>>(s);

    // 5) attention + mean over videos: attn = (1/64) P^T @ V_h (TN, both heads)
    gemm_tn_kernel<<<dim3(HDIM/BN, NTXT/BM, HEADS), 256>>>(
        s, TTOK, (size_t)NVID * TTOK, v, EMBED, HDIM,
        attn, EMBED, HDIM, NVID, 1.f / 64.f);

    // 6) output projection + LN2  (tln reused as scratch)
    gemm_nt_kernel<<<dim3(EMBED/BN, NTXT/BM, 1), 256>>>(
        attn, EMBED, 0, Wo, EMBED, 0, bo, tln, EMBED, 0, EMBED, 1.f);
    ln_kernel<<<NTXT, 256>>>(tln, nullptr, o, ln2_g, ln2_b);

    // 7) linear + residual + LN3
    gemm_nt_kernel<<<dim3(EMBED/BN, NTXT/BM, 1), 256>>>(
        o, EMBED, 0, Wl, EMBED, 0, bl, lin, EMBED, 0, EMBED, 1.f);
    ln_kernel<<<NTXT, 256>>>(o, lin, out, ln3_g, ln3_b);
}

// round 7
// speedup vs baseline: 2.0385x; 1.9226x over previous
#include <cuda_runtime.h>
#include <cuda_bf16.h>
#include <math_constants.h>
#include <cstdint>

typedef unsigned long long u64;

#define EMBED  512
#define HEADS  2
#define HDIM   256
#define NTXT   4096
#define NVID   768
#define FRAMES 12
#define VIDS   64

#define BM 128
#define BN 128
#define BK 32
#define LDT 40                       // 32 + 8 pad bf16 -> 80B row stride (16B-mult, ldmatrix conflict-free)

static const int TILE_B  = 128 * LDT * 2;   // 10240 B per tile
static const int STAGE_B = 4 * TILE_B;      // Ah, Al, Bh, Bl
static const int SMEM_SZ = 2 * STAGE_B;     // 81920 B double-buffered

// ---------------- device scratch ----------------
__device__ float g_s   [HEADS*(size_t)NTXT*NVID];   // logits S'[h][t][v]
__device__ float g_wo  [NTXT*EMBED];
__device__ float g_o   [NTXT*EMBED];
__device__ float g_lin [NTXT*EMBED];

__device__ __nv_bfloat16 g_tln_h[NTXT*EMBED],  g_tln_l[NTXT*EMBED];
__device__ __nv_bfloat16 g_vln_h[NVID*EMBED],  g_vln_l[NVID*EMBED];
__device__ __nv_bfloat16 g_q_h [NTXT*EMBED],   g_q_l [NTXT*EMBED];
__device__ __nv_bfloat16 g_k_h [NVID*EMBED],   g_k_l [NVID*EMBED];
__device__ __nv_bfloat16 g_vt_h[EMBED*NVID],   g_vt_l[EMBED*NVID];
__device__ __nv_bfloat16 g_p_h [HEADS*(size_t)NTXT*NVID], g_p_l[HEADS*(size_t)NTXT*NVID];
__device__ __nv_bfloat16 g_at_h[NTXT*EMBED],   g_at_l[NTXT*EMBED];
__device__ __nv_bfloat16 g_o_h [NTXT*EMBED],   g_o_l [NTXT*EMBED];
__device__ __nv_bfloat16 g_wq_h[EMBED*EMBED],  g_wq_l[EMBED*EMBED];
__device__ __nv_bfloat16 g_wk_h[EMBED*EMBED],  g_wk_l[EMBED*EMBED];
__device__ __nv_bfloat16 g_wv_h[EMBED*EMBED],  g_wv_l[EMBED*EMBED];
__device__ __nv_bfloat16 g_wo_h[EMBED*EMBED],  g_wo_l[EMBED*EMBED];
__device__ __nv_bfloat16 g_wl_h[EMBED*EMBED],  g_wl_l[EMBED*EMBED];

// ---------------- PTX helpers (all baseline sm_80+ instructions) ----------------
__device__ __forceinline__ uint32_t smem_u32(const void* p) {
    uint32_t a;
    asm("{ .reg .u64 t; cvta.to.shared.u64 t, %1; cvt.u32.u64 %0, t; }" : "=r"(a) : "l"(p));
    return a;
}
__device__ __forceinline__ void cpa16(uint32_t d, const void* g) {
    asm volatile("cp.async.cg.shared.global [%0], [%1], 16;" :: "r"(d), "l"(g));
}
__device__ __forceinline__ void ldsm4(uint32_t& r0, uint32_t& r1, uint32_t& r2, uint32_t& r3,
                                      uint32_t a) {
    asm volatile("ldmatrix.sync.aligned.m8n8.x4.shared.b16 {%0,%1,%2,%3}, [%4];"
                 : "=r"(r0), "=r"(r1), "=r"(r2), "=r"(r3) : "r"(a));
}
__device__ __forceinline__ void mma_bf16(float* c, const uint32_t* a, const uint32_t* b) {
    asm volatile("mma.sync.aligned.m16n8k16.row.col.f32.bf16.bf16.f32 "
                 "{%0,%1,%2,%3}, {%4,%5,%6,%7}, {%8,%9}, {%0,%1,%2,%3};"
                 : "+f"(c[0]), "+f"(c[1]), "+f"(c[2]), "+f"(c[3])
                 : "r"(a[0]), "r"(a[1]), "r"(a[2]), "r"(a[3]), "r"(b[0]), "r"(b[1]));
}
__device__ __forceinline__ void split_bf16(float v, __nv_bfloat16& h, __nv_bfloat16& l) {
    h = __float2bfloat16(v);
    l = __float2bfloat16(v - __bfloat162float(h));
}

// ============================================================
// HMMA NT GEMM: C[m,n] = alpha * (Ah+Al)[m,:] . (Bh+Bl)[n,:] (+bias)
// 3-term bf16 split. 128x128x32 tiles, 256 thr, warp-tile 32x64.
// BIASM: 0 none, 1 per-n, 2 per-m.  WF32/WB16: output formats.
// M%128==0, N%128==0, K%32==0.
// ============================================================
template<int BIASM, bool WF32, bool WB16>
__global__ __launch_bounds__(256, 1) void mm_kernel(
    const __nv_bfloat16* __restrict__ Ah, const __nv_bfloat16* __restrict__ Al,
    int lda, int zsA,
    const __nv_bfloat16* __restrict__ Bh, const __nv_bfloat16* __restrict__ Bl,
    int ldb, int zsB,
    const float* __restrict__ bias,
    float* __restrict__ Cf, __nv_bfloat16* __restrict__ Ch, __nv_bfloat16* __restrict__ Cl,
    int ldc, int zsC,
    int K, float alpha)
{
    extern __shared__ char smem[];
    const uint32_t sb = smem_u32(smem);
    const int tid = threadIdx.x, wid = tid >> 5, lane = tid & 31;
    const int z = blockIdx.z;
    const int m0 = blockIdx.y * BM, n0 = blockIdx.x * BN;

    Ah += (size_t)z * zsA;  Al += (size_t)z * zsA;
    Bh += (size_t)z * zsB;  Bl += (size_t)z * zsB;
    if (WF32) Cf += (size_t)z * zsC;
    if (WB16) { Ch += (size_t)z * zsC; Cl += (size_t)z * zsC; }

    const int mw = (wid & 3) * 32;       // warp m offset in tile
    const int nw = (wid >> 2) * 64;      // warp n offset in tile

    // cp.async mapping: 16B per lane, 2 passes per tile
    const int lr = tid >> 2;             // 0..63 row
    const int lc = (tid & 3) * 8;        // bf16 col: 0,8,16,24

    auto load_stage = [&](int s, int buf) {
        const int kb = s * BK;
#pragma unroll
        for (int t = 0; t < 4; t++) {
            const __nv_bfloat16* sp = (t == 0) ? Ah : (t == 1) ? Al : (t == 2) ? Bh : Bl;
            const int r0g = (t < 2) ? m0 : n0;
            const int ld  = (t < 2) ? lda : ldb;
            const uint32_t db = sb + buf * STAGE_B + t * TILE_B;
#pragma unroll
            for (int p = 0; p < 2; p++) {
                const int r = lr + p * 64;
                cpa16(db + (r * LDT + lc) * 2,
                      sp + (size_t)(r0g + r) * ld + kb + lc);
            }
        }
        asm volatile("cp.async.commit_group;" ::: "memory");
    };

    float acc[2][8][4];
#pragma unroll
    for (int i = 0; i < 2; i++)
#pragma unroll
        for (int j = 0; j < 8; j++)
#pragma unroll
            for (int r = 0; r < 4; r++) acc[i][j][r] = 0.f;

    // ldmatrix lane mappings (canonical x4 layouts)
    const int row_a = lane & 15;                       // A: matrices (m0k0,m8k0,m0k8,m8k8)
    const int ka    = (lane >> 4) * 8;
    const int row_b = (lane & 7) + ((lane & 16) >> 1); // B: matrices (n0k0,n0k8,n8k0,n8k8)
    const int kb_   = lane & 8;

    const int S = K / BK;
    int buf = 0;
    load_stage(0, 0);

    for (int s = 0; s < S; s++) {
        if (s + 1 < S) {
            load_stage(s + 1, buf ^ 1);
            asm volatile("cp.async.wait_group 1;" ::: "memory");
        } else {
            asm volatile("cp.async.wait_group 0;" ::: "memory");
        }
        __syncthreads();

        const uint32_t abh = sb + buf * STAGE_B;
        const uint32_t abl = abh + TILE_B;
        const uint32_t bbh = abh + 2 * TILE_B;
        const uint32_t bbl = abh + 3 * TILE_B;

#pragma unroll
        for (int kk = 0; kk < 2; kk++) {
            const int k0 = kk * 16;
            uint32_t ah[2][4], al_[2][4], bh[8][2], bl_[8][2];
#pragma unroll
            for (int mf = 0; mf < 2; mf++) {
                const uint32_t off = ((mw + mf * 16 + row_a) * LDT + k0 + ka) * 2;
                ldsm4(ah[mf][0], ah[mf][1], ah[mf][2], ah[mf][3], abh + off);
                ldsm4(al_[mf][0], al_[mf][1], al_[mf][2], al_[mf][3], abl + off);
            }
#pragma unroll
            for (int p = 0; p < 4; p++) {
                const uint32_t off = ((nw + p * 16 + row_b) * LDT + k0 + kb_) * 2;
                ldsm4(bh[2*p][0], bh[2*p][1], bh[2*p+1][0], bh[2*p+1][1], bbh + off);
                ldsm4(bl_[2*p][0], bl_[2*p][1], bl_[2*p+1][0], bl_[2*p+1][1], bbl + off);
            }
#pragma unroll
            for (int mf = 0; mf < 2; mf++)
#pragma unroll
                for (int nf = 0; nf < 8; nf++) {
                    mma_bf16(acc[mf][nf], ah[mf],  bh[nf]);
                    mma_bf16(acc[mf][nf], ah[mf],  bl_[nf]);
                    mma_bf16(acc[mf][nf], al_[mf], bh[nf]);
                }
        }
        __syncthreads();
        buf ^= 1;
    }

    // ---- epilogue ----
    const int er = lane >> 2, ec = (lane & 3) * 2;
#pragma unroll
    for (int mf = 0; mf < 2; mf++) {
#pragma unroll
        for (int rh = 0; rh < 2; rh++) {
            const int m = m0 + mw + mf * 16 + er + rh * 8;
            const float bm = (BIASM == 2) ? __ldg(bias + m) : 0.f;
#pragma unroll
            for (int nf = 0; nf < 8; nf++) {
                const int n = n0 + nw + nf * 8 + ec;
                float v0 = acc[mf][nf][rh * 2]     * alpha;
                float v1 = acc[mf][nf][rh * 2 + 1] * alpha;
                if (BIASM == 1) { v0 += __ldg(bias + n); v1 += __ldg(bias + n + 1); }
                if (BIASM == 2) { v0 += bm; v1 += bm; }
                if (WF32)
                    *(float2*)(Cf + (size_t)m * ldc + n) = make_float2(v0, v1);
                if (WB16) {
                    __nv_bfloat16 h0, l0, h1, l1;
                    split_bf16(v0, h0, l0);
                    split_bf16(v1, h1, l1);
                    __nv_bfloat162 hh(h0, h1), ll(l0, l1);
                    *(uint32_t*)(Ch + (size_t)m * ldc + n) = *(uint32_t*)&hh;
                    *(uint32_t*)(Cl + (size_t)m * ldc + n) = *(uint32_t*)&ll;
                }
            }
        }
    }
}

// ============================================================
// LayerNorm (rows of 512). Optional residual x2; fp32 / bf16-hi/lo outputs.
// ============================================================
template<bool W32, bool W16, bool HAS2>
__global__ __launch_bounds__(256) void ln_k(
    const float* __restrict__ x, const float* __restrict__ x2,
    float* __restrict__ yf, __nv_bfloat16* __restrict__ yh, __nv_bfloat16* __restrict__ yl,
    const float* __restrict__ g, const float* __restrict__ b)
{
    int row = blockIdx.x, t = threadIdx.x;
    float2 v = ((const float2*)(x + (size_t)row * EMBED))[t];
    if (HAS2) {
        float2 w = ((const float2*)(x2 + (size_t)row * EMBED))[t];
        v.x += w.x; v.y += w.y;
    }
    float s = v.x + v.y, s2 = v.x * v.x + v.y * v.y;
#pragma unroll
    for (int o = 16; o; o >>= 1) {
        s  += __shfl_xor_sync(0xffffffffu, s,  o);
        s2 += __shfl_xor_sync(0xffffffffu, s2, o);
    }
    __shared__ float rs[8], rs2[8];
    if ((t & 31) == 0) { rs[t >> 5] = s; rs2[t >> 5] = s2; }
    __syncthreads();
    if (t < 32) {
        float a  = t < 8 ? rs[t]  : 0.f;
        float a2 = t < 8 ? rs2[t] : 0.f;
#pragma unroll
        for (int o = 4; o; o >>= 1) {
            a  += __shfl_xor_sync(0xffffffffu, a,  o);
            a2 += __shfl_xor_sync(0xffffffffu, a2, o);
        }
        if (t == 0) { rs[0] = a; rs2[0] = a2; }
    }
    __syncthreads();
    float mu  = rs[0]  * (1.f / EMBED);
    float var = rs2[0] * (1.f / EMBED) - mu * mu;
    float inv = rsqrtf(var + 1e-5f);
    float2 gg = ((const float2*)g)[t], bb = ((const float2*)b)[t];
    float2 r = make_float2((v.x - mu) * inv * gg.x + bb.x,
                           (v.y - mu) * inv * gg.y + bb.y);
    if (W32) ((float2*)(yf + (size_t)row * EMBED))[t] = r;
    if (W16) {
        __nv_bfloat16 h0, l0, h1, l1;
        split_bf16(r.x, h0, l0);
        split_bf16(r.y, h1, l1);
        __nv_bfloat162 hh(h0, h1), ll(l0, l1);
        ((uint32_t*)(yh + (size_t)row * EMBED))[t] = *(uint32_t*)&hh;
        ((uint32_t*)(yl + (size_t)row * EMBED))[t] = *(uint32_t*)&ll;
    }
}

// ============================================================
// Softmax over 12 contiguous frames: S'[h][t][a*12+f] -> P hi/lo bf16.
// ============================================================
__global__ __launch_bounds__(256) void softmax_k(
    const float* __restrict__ S, __nv_bfloat16* __restrict__ Ph, __nv_bfloat16* __restrict__ Pl)
{
    int idx = blockIdx.x * 256 + threadIdx.x;          // ((h*4096+t)*64 + a)
    size_t off = (size_t)(idx >> 6) * NVID + (idx & 63) * FRAMES;
    const float* base = S + off;
    float4 v0 = *(const float4*)(base);
    float4 v1 = *(const float4*)(base + 4);
    float4 v2 = *(const float4*)(base + 8);
    float vl[12] = {v0.x,v0.y,v0.z,v0.w, v1.x,v1.y,v1.z,v1.w, v2.x,v2.y,v2.z,v2.w};
    float m = -CUDART_INF_F;
#pragma unroll
    for (int f = 0; f < 12; f++) m = fmaxf(m, vl[f]);
    float sum = 0.f;
#pragma unroll
    for (int f = 0; f < 12; f++) { vl[f] = __expf(vl[f] - m); sum += vl[f]; }
    float inv = 1.f / sum;
    uint32_t hp[6], lp[6];
#pragma unroll
    for (int g = 0; g < 6; g++) {
        __nv_bfloat16 h0, l0, h1, l1;
        split_bf16(vl[2*g]   * inv, h0, l0);
        split_bf16(vl[2*g+1] * inv, h1, l1);
        __nv_bfloat162 hh(h0, h1), ll(l0, l1);
        hp[g] = *(uint32_t*)&hh;  lp[g] = *(uint32_t*)&ll;
    }
#pragma unroll
    for (int g = 0; g < 3; g++) {
        *(uint2*)(Ph + off + g * 4) = make_uint2(hp[2*g], hp[2*g+1]);
        *(uint2*)(Pl + off + g * 4) = make_uint2(lp[2*g], lp[2*g+1]);
    }
}

// fp32 -> bf16 hi/lo converter (weights)
__global__ __launch_bounds__(256) void conv_k(
    const float* __restrict__ s, __nv_bfloat16* __restrict__ h, __nv_bfloat16* __restrict__ l)
{
    int i = (blockIdx.x * 256 + threadIdx.x) * 2;
    float2 v = *(const float2*)(s + i);
    __nv_bfloat16 h0, l0, h1, l1;
    split_bf16(v.x, h0, l0);
    split_bf16(v.y, h1, l1);
    __nv_bfloat162 hh(h0, h1), ll(l0, l1);
    *(uint32_t*)(h + i) = *(uint32_t*)&hh;
    *(uint32_t*)(l + i) = *(uint32_t*)&ll;
}

// ============================================================
extern "C" void kernel_launch(void* const* d_in, const int* in_sizes, int n_in,
                              void* d_out, int out_size)
{
    const float* text  = (const float*)d_in[0];
    const float* video = (const float*)d_in[1];
    const float* ln1_g = (const float*)d_in[2];
    const float* ln1_b = (const float*)d_in[3];
    const float* Wq    = (const float*)d_in[4];
    const float* bq    = (const float*)d_in[5];
    const float* Wk    = (const float*)d_in[6];
    const float* bk    = (const float*)d_in[7];
    const float* Wv    = (const float*)d_in[8];
    const float* bv    = (const float*)d_in[9];
    const float* Wo    = (const float*)d_in[10];
    const float* bo    = (const float*)d_in[11];
    const float* Wl    = (const float*)d_in[12];
    const float* bl    = (const float*)d_in[13];
    const float* ln2_g = (const float*)d_in[14];
    const float* ln2_b = (const float*)d_in[15];
    const float* ln3_g = (const float*)d_in[16];
    const float* ln3_b = (const float*)d_in[17];
    float* out = (float*)d_out;

    float *s, *wo, *o, *lin;
    __nv_bfloat16 *tlnh,*tlnl,*vlnh,*vlnl,*qh,*ql,*kh,*kl,*vth,*vtl,*ph,*pl,*ath,*atl,*oh,*ol;
    __nv_bfloat16 *wqh,*wql,*wkh,*wkl,*wvh,*wvl,*woh,*wol,*wlh,*wll;
    cudaGetSymbolAddress((void**)&s,    g_s);
    cudaGetSymbolAddress((void**)&wo,   g_wo);
    cudaGetSymbolAddress((void**)&o,    g_o);
    cudaGetSymbolAddress((void**)&lin,  g_lin);
    cudaGetSymbolAddress((void**)&tlnh, g_tln_h); cudaGetSymbolAddress((void**)&tlnl, g_tln_l);
    cudaGetSymbolAddress((void**)&vlnh, g_vln_h); cudaGetSymbolAddress((void**)&vlnl, g_vln_l);
    cudaGetSymbolAddress((void**)&qh,  g_q_h);  cudaGetSymbolAddress((void**)&ql,  g_q_l);
    cudaGetSymbolAddress((void**)&kh,  g_k_h);  cudaGetSymbolAddress((void**)&kl,  g_k_l);
    cudaGetSymbolAddress((void**)&vth, g_vt_h); cudaGetSymbolAddress((void**)&vtl, g_vt_l);
    cudaGetSymbolAddress((void**)&ph,  g_p_h);  cudaGetSymbolAddress((void**)&pl,  g_p_l);
    cudaGetSymbolAddress((void**)&ath, g_at_h); cudaGetSymbolAddress((void**)&atl, g_at_l);
    cudaGetSymbolAddress((void**)&oh,  g_o_h);  cudaGetSymbolAddress((void**)&ol,  g_o_l);
    cudaGetSymbolAddress((void**)&wqh, g_wq_h); cudaGetSymbolAddress((void**)&wql, g_wq_l);
    cudaGetSymbolAddress((void**)&wkh, g_wk_h); cudaGetSymbolAddress((void**)&wkl, g_wk_l);
    cudaGetSymbolAddress((void**)&wvh, g_wv_h); cudaGetSymbolAddress((void**)&wvl, g_wv_l);
    cudaGetSymbolAddress((void**)&woh, g_wo_h); cudaGetSymbolAddress((void**)&wol, g_wo_l);
    cudaGetSymbolAddress((void**)&wlh, g_wl_h); cudaGetSymbolAddress((void**)&wll, g_wl_l);

    cudaFuncSetAttribute(mm_kernel<1,false,true>, cudaFuncAttributeMaxDynamicSharedMemorySize, SMEM_SZ);
    cudaFuncSetAttribute(mm_kernel<2,false,true>, cudaFuncAttributeMaxDynamicSharedMemorySize, SMEM_SZ);
    cudaFuncSetAttribute(mm_kernel<0,true,false>, cudaFuncAttributeMaxDynamicSharedMemorySize, SMEM_SZ);
    cudaFuncSetAttribute(mm_kernel<0,false,true>, cudaFuncAttributeMaxDynamicSharedMemorySize, SMEM_SZ);
    cudaFuncSetAttribute(mm_kernel<1,true,false>, cudaFuncAttributeMaxDynamicSharedMemorySize, SMEM_SZ);

    const int WN = EMBED * EMBED / 512;

    // 0) weights -> bf16 hi/lo
    conv_k<<<WN, 256>>>(Wq, wqh, wql);
    conv_k<<<WN, 256>>>(Wk, wkh, wkl);
    conv_k<<<WN, 256>>>(Wv, wvh, wvl);
    conv_k<<<WN, 256>>>(Wo, woh, wol);
    conv_k<<<WN, 256>>>(Wl, wlh, wll);

    // 1) LN1 -> bf16 hi/lo
    ln_k<false,true,false><<<NTXT, 256>>>(text,  nullptr, nullptr, tlnh, tlnl, ln1_g, ln1_b);
    ln_k<false,true,false><<<NVID, 256>>>(video, nullptr, nullptr, vlnh, vlnl, ln1_g, ln1_b);

    // 2) Q = tln @ Wq^T + bq [4096x512]; K = vln @ Wk^T + bk [768x512];
    //    Vt[d, vm] = Wv @ vln^T + bv(per-m) [512x768]
    mm_kernel<1,false,true><<<dim3(EMBED/BN, NTXT/BM, 1), 256, SMEM_SZ>>>(
        tlnh, tlnl, EMBED, 0, wqh, wql, EMBED, 0, bq,
        nullptr, qh, ql, EMBED, 0, EMBED, 1.f);
    mm_kernel<1,false,true><<<dim3(EMBED/BN, NVID/BM, 1), 256, SMEM_SZ>>>(
        vlnh, vlnl, EMBED, 0, wkh, wkl, EMBED, 0, bk,
        nullptr, kh, kl, EMBED, 0, EMBED, 1.f);
    mm_kernel<2,false,true><<<dim3(NVID/BN, EMBED/BM, 1), 256, SMEM_SZ>>>(
        wvh, wvl, EMBED, 0, vlnh, vlnl, EMBED, 0, bv,
        nullptr, vth, vtl, NVID, 0, EMBED, 1.f);

    // 3) logits S'[h][t][v] = (1/16) Q_h @ K_h^T  [4096x768], z = head
    mm_kernel<0,true,false><<<dim3(NVID/BN, NTXT/BM, HEADS), 256, SMEM_SZ>>>(
        qh, ql, EMBED, HDIM, kh, kl, EMBED, HDIM, nullptr,
        s, nullptr, nullptr, NVID, NTXT*NVID, HDIM, 1.f/16.f);

    // 4) softmax over 12 frames -> P hi/lo
    softmax_k<<<(HEADS * NTXT * VIDS) / 256, 256>>>(s, ph, pl);

    // 5) attn[t, h*256+d] = (1/64) P_h @ Vt_h^T [4096x256], z = head
    mm_kernel<0,false,true><<<dim3(HDIM/BN, NTXT/BM, HEADS), 256, SMEM_SZ>>>(
        ph, pl, NVID, NTXT*NVID, vth, vtl, NVID, HDIM*NVID, nullptr,
        nullptr, ath, atl, EMBED, HDIM, NVID, 1.f/64.f);

    // 6) Wo projection -> fp32, then LN2 (fp32 + bf16 hi/lo)
    mm_kernel<1,true,false><<<dim3(EMBED/BN, NTXT/BM, 1), 256, SMEM_SZ>>>(
        ath, atl, EMBED, 0, woh, wol, EMBED, 0, bo,
        wo, nullptr, nullptr, EMBED, 0, EMBED, 1.f);
    ln_k<true,true,false><<<NTXT, 256>>>(wo, nullptr, o, oh, ol, ln2_g, ln2_b);

    // 7) Wl linear -> fp32, then residual + LN3 -> out
    mm_kernel<1,true,false><<<dim3(EMBED/BN, NTXT/BM, 1), 256, SMEM_SZ>>>(
        oh, ol, EMBED, 0, wlh, wll, EMBED, 0, bl,
        lin, nullptr, nullptr, EMBED, 0, EMBED, 1.f);
    ln_k<true,false,true><<<NTXT, 256>>>(o, lin, out, nullptr, nullptr, ln3_g, ln3_b);
}

// round 10
// speedup vs baseline: 2.2863x; 1.1216x over previous
#include <cuda_runtime.h>
#include <cuda_bf16.h>
#include <math_constants.h>
#include <cstdint>

typedef unsigned long long u64;

#define EMBED  512
#define HEADS  2
#define HDIM   256
#define NTXT   4096
#define NVID   768
#define FRAMES 12
#define VIDS   64

#define BM 128
#define BN 128
#define BK 32
#define LDT 40                       // 32 + 8 pad bf16 -> 80B row stride (16B-mult, ldmatrix conflict-free)

static const int TILE_B  = 128 * LDT * 2;   // 10240 B per tile
static const int STAGE_B = 4 * TILE_B;      // Ah, Al, Bh, Bl
static const int SMEM_SZ = 2 * STAGE_B;     // 81920 B double-buffered

// ---------------- device scratch ----------------
__device__ float g_s   [HEADS*(size_t)NTXT*NVID];   // logits S'[h][t][v]
__device__ float g_wo  [NTXT*EMBED];
__device__ float g_o   [NTXT*EMBED];
__device__ float g_lin [NTXT*EMBED];

__device__ __nv_bfloat16 g_tln_h[NTXT*EMBED],  g_tln_l[NTXT*EMBED];
__device__ __nv_bfloat16 g_vln_h[NVID*EMBED],  g_vln_l[NVID*EMBED];
__device__ __nv_bfloat16 g_q_h [NTXT*EMBED],   g_q_l [NTXT*EMBED];
__device__ __nv_bfloat16 g_k_h [NVID*EMBED],   g_k_l [NVID*EMBED];
__device__ __nv_bfloat16 g_vt_h[EMBED*NVID],   g_vt_l[EMBED*NVID];
__device__ __nv_bfloat16 g_p_h [HEADS*(size_t)NTXT*NVID], g_p_l[HEADS*(size_t)NTXT*NVID];
__device__ __nv_bfloat16 g_at_h[NTXT*EMBED],   g_at_l[NTXT*EMBED];
__device__ __nv_bfloat16 g_o_h [NTXT*EMBED],   g_o_l [NTXT*EMBED];
__device__ __nv_bfloat16 g_wq_h[EMBED*EMBED],  g_wq_l[EMBED*EMBED];
__device__ __nv_bfloat16 g_wk_h[EMBED*EMBED],  g_wk_l[EMBED*EMBED];
__device__ __nv_bfloat16 g_wv_h[EMBED*EMBED],  g_wv_l[EMBED*EMBED];
__device__ __nv_bfloat16 g_wo_h[EMBED*EMBED],  g_wo_l[EMBED*EMBED];
__device__ __nv_bfloat16 g_wl_h[EMBED*EMBED],  g_wl_l[EMBED*EMBED];

// ---------------- PTX helpers (all baseline sm_80+ instructions) ----------------
__device__ __forceinline__ uint32_t smem_u32(const void* p) {
    uint32_t a;
    asm("{ .reg .u64 t; cvta.to.shared.u64 t, %1; cvt.u32.u64 %0, t; }" : "=r"(a) : "l"(p));
    return a;
}
__device__ __forceinline__ void cpa16(uint32_t d, const void* g) {
    asm volatile("cp.async.cg.shared.global [%0], [%1], 16;" :: "r"(d), "l"(g));
}
__device__ __forceinline__ void ldsm4(uint32_t& r0, uint32_t& r1, uint32_t& r2, uint32_t& r3,
                                      uint32_t a) {
    asm volatile("ldmatrix.sync.aligned.m8n8.x4.shared.b16 {%0,%1,%2,%3}, [%4];"
                 : "=r"(r0), "=r"(r1), "=r"(r2), "=r"(r3) : "r"(a));
}
__device__ __forceinline__ void mma_bf16(float* c, const uint32_t* a, const uint32_t* b) {
    asm volatile("mma.sync.aligned.m16n8k16.row.col.f32.bf16.bf16.f32 "
                 "{%0,%1,%2,%3}, {%4,%5,%6,%7}, {%8,%9}, {%0,%1,%2,%3};"
                 : "+f"(c[0]), "+f"(c[1]), "+f"(c[2]), "+f"(c[3])
                 : "r"(a[0]), "r"(a[1]), "r"(a[2]), "r"(a[3]), "r"(b[0]), "r"(b[1]));
}
__device__ __forceinline__ void split_bf16(float v, __nv_bfloat16& h, __nv_bfloat16& l) {
    h = __float2bfloat16(v);
    l = __float2bfloat16(v - __bfloat162float(h));
}

// ============================================================
// HMMA NT GEMM core (R7 winner, unchanged).
// C[m,n] = alpha * (Ah+Al)[m,:].(Bh+Bl)[n,:] (+bias), 3-term bf16 split.
// 128x128x32 tiles, 256 thr, warp-tile 32x64.
// BIASM: 0 none, 1 per-n, 2 per-m.  WF32/WB16: output formats.
// ============================================================
template<int BIASM, bool WF32, bool WB16>
__device__ __forceinline__ void mm_core(
    const __nv_bfloat16* __restrict__ Ah, const __nv_bfloat16* __restrict__ Al, int lda,
    const __nv_bfloat16* __restrict__ Bh, const __nv_bfloat16* __restrict__ Bl, int ldb,
    const float* __restrict__ bias,
    float* __restrict__ Cf, __nv_bfloat16* __restrict__ Ch, __nv_bfloat16* __restrict__ Cl,
    int ldc, int K, float alpha, int m0, int n0, char* smem)
{
    const uint32_t sb = smem_u32(smem);
    const int tid = threadIdx.x, wid = tid >> 5, lane = tid & 31;

    const int mw = (wid & 3) * 32;       // warp m offset in tile
    const int nw = (wid >> 2) * 64;      // warp n offset in tile

    const int lr = tid >> 2;             // 0..63 row
    const int lc = (tid & 3) * 8;        // bf16 col: 0,8,16,24

    auto load_stage = [&](int s, int buf) {
        const int kb = s * BK;
#pragma unroll
        for (int t = 0; t < 4; t++) {
            const __nv_bfloat16* sp = (t == 0) ? Ah : (t == 1) ? Al : (t == 2) ? Bh : Bl;
            const int r0g = (t < 2) ? m0 : n0;
            const int ld  = (t < 2) ? lda : ldb;
            const uint32_t db = sb + buf * STAGE_B + t * TILE_B;
#pragma unroll
            for (int p = 0; p < 2; p++) {
                const int r = lr + p * 64;
                cpa16(db + (r * LDT + lc) * 2,
                      sp + (size_t)(r0g + r) * ld + kb + lc);
            }
        }
        asm volatile("cp.async.commit_group;" ::: "memory");
    };

    float acc[2][8][4];
#pragma unroll
    for (int i = 0; i < 2; i++)
#pragma unroll
        for (int j = 0; j < 8; j++)
#pragma unroll
            for (int r = 0; r < 4; r++) acc[i][j][r] = 0.f;

    const int row_a = lane & 15;
    const int ka    = (lane >> 4) * 8;
    const int row_b = (lane & 7) + ((lane & 16) >> 1);
    const int kb_   = lane & 8;

    const int S = K / BK;
    int buf = 0;
    load_stage(0, 0);

    for (int s = 0; s < S; s++) {
        if (s + 1 < S) {
            load_stage(s + 1, buf ^ 1);
            asm volatile("cp.async.wait_group 1;" ::: "memory");
        } else {
            asm volatile("cp.async.wait_group 0;" ::: "memory");
        }
        __syncthreads();

        const uint32_t abh = sb + buf * STAGE_B;
        const uint32_t abl = abh + TILE_B;
        const uint32_t bbh = abh + 2 * TILE_B;
        const uint32_t bbl = abh + 3 * TILE_B;

#pragma unroll
        for (int kk = 0; kk < 2; kk++) {
            const int k0 = kk * 16;
            uint32_t ah[2][4], al_[2][4], bh[8][2], bl_[8][2];
#pragma unroll
            for (int mf = 0; mf < 2; mf++) {
                const uint32_t off = ((mw + mf * 16 + row_a) * LDT + k0 + ka) * 2;
                ldsm4(ah[mf][0], ah[mf][1], ah[mf][2], ah[mf][3], abh + off);
                ldsm4(al_[mf][0], al_[mf][1], al_[mf][2], al_[mf][3], abl + off);
            }
#pragma unroll
            for (int p = 0; p < 4; p++) {
                const uint32_t off = ((nw + p * 16 + row_b) * LDT + k0 + kb_) * 2;
                ldsm4(bh[2*p][0], bh[2*p][1], bh[2*p+1][0], bh[2*p+1][1], bbh + off);
                ldsm4(bl_[2*p][0], bl_[2*p][1], bl_[2*p+1][0], bl_[2*p+1][1], bbl + off);
            }
#pragma unroll
            for (int mf = 0; mf < 2; mf++)
#pragma unroll
                for (int nf = 0; nf < 8; nf++) {
                    mma_bf16(acc[mf][nf], ah[mf],  bh[nf]);
                    mma_bf16(acc[mf][nf], ah[mf],  bl_[nf]);
                    mma_bf16(acc[mf][nf], al_[mf], bh[nf]);
                }
        }
        __syncthreads();
        buf ^= 1;
    }

    // ---- epilogue ----
    const int er = lane >> 2, ec = (lane & 3) * 2;
#pragma unroll
    for (int mf = 0; mf < 2; mf++) {
#pragma unroll
        for (int rh = 0; rh < 2; rh++) {
            const int m = m0 + mw + mf * 16 + er + rh * 8;
            const float bm = (BIASM == 2) ? __ldg(bias + m) : 0.f;
#pragma unroll
            for (int nf = 0; nf < 8; nf++) {
                const int n = n0 + nw + nf * 8 + ec;
                float v0 = acc[mf][nf][rh * 2]     * alpha;
                float v1 = acc[mf][nf][rh * 2 + 1] * alpha;
                if (BIASM == 1) { v0 += __ldg(bias + n); v1 += __ldg(bias + n + 1); }
                if (BIASM == 2) { v0 += bm; v1 += bm; }
                if (WF32)
                    *(float2*)(Cf + (size_t)m * ldc + n) = make_float2(v0, v1);
                if (WB16) {
                    __nv_bfloat16 h0, l0, h1, l1;
                    split_bf16(v0, h0, l0);
                    split_bf16(v1, h1, l1);
                    __nv_bfloat162 hh(h0, h1), ll(l0, l1);
                    *(uint32_t*)(Ch + (size_t)m * ldc + n) = *(uint32_t*)&hh;
                    *(uint32_t*)(Cl + (size_t)m * ldc + n) = *(uint32_t*)&ll;
                }
            }
        }
    }
}

// ---- GEMM kernel wrappers ----
template<int BIASM, bool WF32, bool WB16>
__global__ __launch_bounds__(256, 1) void mm_kernel(
    const __nv_bfloat16* __restrict__ Ah, const __nv_bfloat16* __restrict__ Al,
    int lda, int zsA,
    const __nv_bfloat16* __restrict__ Bh, const __nv_bfloat16* __restrict__ Bl,
    int ldb, int zsB,
    const float* __restrict__ bias,
    float* __restrict__ Cf, __nv_bfloat16* __restrict__ Ch, __nv_bfloat16* __restrict__ Cl,
    int ldc, int zsC,
    int K, float alpha)
{
    extern __shared__ char smem[];
    const int z = blockIdx.z;
    Ah += (size_t)z * zsA;  Al += (size_t)z * zsA;
    Bh += (size_t)z * zsB;  Bl += (size_t)z * zsB;
    if (WF32) Cf += (size_t)z * zsC;
    if (WB16) { Ch += (size_t)z * zsC; Cl += (size_t)z * zsC; }
    mm_core<BIASM, WF32, WB16>(Ah, Al, lda, Bh, Bl, ldb, bias, Cf, Ch, Cl,
                               ldc, K, alpha, blockIdx.y * BM, blockIdx.x * BN, smem);
}

// fused Q / K / Vt projections in one launch (z = 0:Q, 1:K, 2:Vt)
// Launched with grid = (6, 32, 3) = max over jobs; every job guards BOTH x and y.
//   Q : [4096 x 512], K=512 -> x<4,  y<32
//   K : [ 768 x 512], K=512 -> x<4,  y<6
//   Vt: [ 512 x 768], K=512 -> x<6,  y<4
__global__ __launch_bounds__(256, 1) void qkv_kernel(
    const __nv_bfloat16* __restrict__ tlnh, const __nv_bfloat16* __restrict__ tlnl,
    const __nv_bfloat16* __restrict__ vlnh, const __nv_bfloat16* __restrict__ vlnl,
    const __nv_bfloat16* __restrict__ wqh,  const __nv_bfloat16* __restrict__ wql,
    const __nv_bfloat16* __restrict__ wkh,  const __nv_bfloat16* __restrict__ wkl,
    const __nv_bfloat16* __restrict__ wvh,  const __nv_bfloat16* __restrict__ wvl,
    const float* __restrict__ bq, const float* __restrict__ bk, const float* __restrict__ bv,
    __nv_bfloat16* __restrict__ qh,  __nv_bfloat16* __restrict__ ql,
    __nv_bfloat16* __restrict__ kh,  __nv_bfloat16* __restrict__ kl,
    __nv_bfloat16* __restrict__ vth, __nv_bfloat16* __restrict__ vtl)
{
    extern __shared__ char smem[];
    const int z = blockIdx.z;
    const int bx = blockIdx.x, by = blockIdx.y;
    const int m0 = by * BM, n0 = bx * BN;
    if (z == 0) {
        if (bx >= EMBED / BN || by >= NTXT / BM) return;
        // Q = tln @ Wq^T + bq   [4096 x 512], per-n bias, contraction K = EMBED
        mm_core<1,false,true>(tlnh, tlnl, EMBED, wqh, wql, EMBED, bq,
                              nullptr, qh, ql, EMBED, EMBED, 1.f, m0, n0, smem);
    } else if (z == 1) {
        if (bx >= EMBED / BN || by >= NVID / BM) return;
        // K = vln @ Wk^T + bk   [768 x 512], per-n bias, contraction K = EMBED
        mm_core<1,false,true>(vlnh, vlnl, EMBED, wkh, wkl, EMBED, bk,
                              nullptr, kh, kl, EMBED, EMBED, 1.f, m0, n0, smem);
    } else {
        if (bx >= NVID / BN || by >= EMBED / BM) return;
        // Vt[d, vm] = Wv @ vln^T + bv (per-m bias)  [512 x 768]
        // ldc = NVID (768-wide output rows), contraction K = EMBED = 512  <-- R9 bug was K=NVID
        mm_core<2,false,true>(wvh, wvl, EMBED, vlnh, vlnl, EMBED, bv,
                              nullptr, vth, vtl, NVID, EMBED, 1.f, m0, n0, smem);
    }
}

// ============================================================
// LayerNorm (rows of 512). Optional residual x2; fp32 / bf16-hi/lo outputs.
// ============================================================
template<bool W32, bool W16, bool HAS2>
__device__ __forceinline__ void ln_core(
    const float* __restrict__ x, const float* __restrict__ x2,
    float* __restrict__ yf, __nv_bfloat16* __restrict__ yh, __nv_bfloat16* __restrict__ yl,
    const float* __restrict__ g, const float* __restrict__ b, int row)
{
    int t = threadIdx.x;
    float2 v = ((const float2*)(x + (size_t)row * EMBED))[t];
    if (HAS2) {
        float2 w = ((const float2*)(x2 + (size_t)row * EMBED))[t];
        v.x += w.x; v.y += w.y;
    }
    float s = v.x + v.y, s2 = v.x * v.x + v.y * v.y;
#pragma unroll
    for (int o = 16; o; o >>= 1) {
        s  += __shfl_xor_sync(0xffffffffu, s,  o);
        s2 += __shfl_xor_sync(0xffffffffu, s2, o);
    }
    __shared__ float rs[8], rs2[8];
    if ((t & 31) == 0) { rs[t >> 5] = s; rs2[t >> 5] = s2; }
    __syncthreads();
    if (t < 32) {
        float a  = t < 8 ? rs[t]  : 0.f;
        float a2 = t < 8 ? rs2[t] : 0.f;
#pragma unroll
        for (int o = 4; o; o >>= 1) {
            a  += __shfl_xor_sync(0xffffffffu, a,  o);
            a2 += __shfl_xor_sync(0xffffffffu, a2, o);
        }
        if (t == 0) { rs[0] = a; rs2[0] = a2; }
    }
    __syncthreads();
    float mu  = rs[0]  * (1.f / EMBED);
    float var = rs2[0] * (1.f / EMBED) - mu * mu;
    float inv = rsqrtf(var + 1e-5f);
    float2 gg = ((const float2*)g)[t], bb = ((const float2*)b)[t];
    float2 r = make_float2((v.x - mu) * inv * gg.x + bb.x,
                           (v.y - mu) * inv * gg.y + bb.y);
    if (W32) ((float2*)(yf + (size_t)row * EMBED))[t] = r;
    if (W16) {
        __nv_bfloat16 h0, l0, h1, l1;
        split_bf16(r.x, h0, l0);
        split_bf16(r.y, h1, l1);
        __nv_bfloat162 hh(h0, h1), ll(l0, l1);
        ((uint32_t*)(yh + (size_t)row * EMBED))[t] = *(uint32_t*)&hh;
        ((uint32_t*)(yl + (size_t)row * EMBED))[t] = *(uint32_t*)&ll;
    }
}

template<bool W32, bool W16, bool HAS2>
__global__ __launch_bounds__(256) void ln_k(
    const float* __restrict__ x, const float* __restrict__ x2,
    float* __restrict__ yf, __nv_bfloat16* __restrict__ yh, __nv_bfloat16* __restrict__ yl,
    const float* __restrict__ g, const float* __restrict__ b)
{
    ln_core<W32, W16, HAS2>(x, x2, yf, yh, yl, g, b, blockIdx.x);
}

// fused LN1 over text (rows 0..4095) + video (rows 4096..4863)
__global__ __launch_bounds__(256) void ln1_k(
    const float* __restrict__ text, const float* __restrict__ video,
    __nv_bfloat16* __restrict__ tlnh, __nv_bfloat16* __restrict__ tlnl,
    __nv_bfloat16* __restrict__ vlnh, __nv_bfloat16* __restrict__ vlnl,
    const float* __restrict__ g, const float* __restrict__ b)
{
    int row = blockIdx.x;
    if (row < NTXT)
        ln_core<false,true,false>(text, nullptr, nullptr, tlnh, tlnl, g, b, row);
    else
        ln_core<false,true,false>(video, nullptr, nullptr, vlnh, vlnl, g, b, row - NTXT);
}

// ============================================================
// Softmax over 12 contiguous frames: S'[h][t][a*12+f] -> P hi/lo bf16.
// ============================================================
__global__ __launch_bounds__(256) void softmax_k(
    const float* __restrict__ S, __nv_bfloat16* __restrict__ Ph, __nv_bfloat16* __restrict__ Pl)
{
    int idx = blockIdx.x * 256 + threadIdx.x;          // ((h*4096+t)*64 + a)
    size_t off = (size_t)(idx >> 6) * NVID + (idx & 63) * FRAMES;
    const float* base = S + off;
    float4 v0 = *(const float4*)(base);
    float4 v1 = *(const float4*)(base + 4);
    float4 v2 = *(const float4*)(base + 8);
    float vl[12] = {v0.x,v0.y,v0.z,v0.w, v1.x,v1.y,v1.z,v1.w, v2.x,v2.y,v2.z,v2.w};
    float m = -CUDART_INF_F;
#pragma unroll
    for (int f = 0; f < 12; f++) m = fmaxf(m, vl[f]);
    float sum = 0.f;
#pragma unroll
    for (int f = 0; f < 12; f++) { vl[f] = __expf(vl[f] - m); sum += vl[f]; }
    float inv = 1.f / sum;
    uint32_t hp[6], lp[6];
#pragma unroll
    for (int g = 0; g < 6; g++) {
        __nv_bfloat16 h0, l0, h1, l1;
        split_bf16(vl[2*g]   * inv, h0, l0);
        split_bf16(vl[2*g+1] * inv, h1, l1);
        __nv_bfloat162 hh(h0, h1), ll(l0, l1);
        hp[g] = *(uint32_t*)&hh;  lp[g] = *(uint32_t*)&ll;
    }
#pragma unroll
    for (int g = 0; g < 3; g++) {
        *(uint2*)(Ph + off + g * 4) = make_uint2(hp[2*g], hp[2*g+1]);
        *(uint2*)(Pl + off + g * 4) = make_uint2(lp[2*g], lp[2*g+1]);
    }
}

// fused fp32 -> bf16 hi/lo converter for ALL 5 weights (grid.y selects weight)
__global__ __launch_bounds__(256) void conv5_k(
    const float* __restrict__ s0, __nv_bfloat16* __restrict__ h0, __nv_bfloat16* __restrict__ l0,
    const float* __restrict__ s1, __nv_bfloat16* __restrict__ h1, __nv_bfloat16* __restrict__ l1,
    const float* __restrict__ s2, __nv_bfloat16* __restrict__ h2, __nv_bfloat16* __restrict__ l2,
    const float* __restrict__ s3, __nv_bfloat16* __restrict__ h3, __nv_bfloat16* __restrict__ l3,
    const float* __restrict__ s4, __nv_bfloat16* __restrict__ h4, __nv_bfloat16* __restrict__ l4)
{
    const float* s; __nv_bfloat16 *h, *l;
    switch (blockIdx.y) {
        case 0: s = s0; h = h0; l = l0; break;
        case 1: s = s1; h = h1; l = l1; break;
        case 2: s = s2; h = h2; l = l2; break;
        case 3: s = s3; h = h3; l = l3; break;
        default: s = s4; h = h4; l = l4; break;
    }
    int i = (blockIdx.x * 256 + threadIdx.x) * 2;
    float2 v = *(const float2*)(s + i);
    __nv_bfloat16 ha, la, hb, lb;
    split_bf16(v.x, ha, la);
    split_bf16(v.y, hb, lb);
    __nv_bfloat162 hh(ha, hb), ll(la, lb);
    *(uint32_t*)(h + i) = *(uint32_t*)&hh;
    *(uint32_t*)(l + i) = *(uint32_t*)&ll;
}

// ============================================================
extern "C" void kernel_launch(void* const* d_in, const int* in_sizes, int n_in,
                              void* d_out, int out_size)
{
    const float* text  = (const float*)d_in[0];
    const float* video = (const float*)d_in[1];
    const float* ln1_g = (const float*)d_in[2];
    const float* ln1_b = (const float*)d_in[3];
    const float* Wq    = (const float*)d_in[4];
    const float* bq    = (const float*)d_in[5];
    const float* Wk    = (const float*)d_in[6];
    const float* bk    = (const float*)d_in[7];
    const float* Wv    = (const float*)d_in[8];
    const float* bv    = (const float*)d_in[9];
    const float* Wo    = (const float*)d_in[10];
    const float* bo    = (const float*)d_in[11];
    const float* Wl    = (const float*)d_in[12];
    const float* bl    = (const float*)d_in[13];
    const float* ln2_g = (const float*)d_in[14];
    const float* ln2_b = (const float*)d_in[15];
    const float* ln3_g = (const float*)d_in[16];
    const float* ln3_b = (const float*)d_in[17];
    float* out = (float*)d_out;

    float *s, *wo, *o, *lin;
    __nv_bfloat16 *tlnh,*tlnl,*vlnh,*vlnl,*qh,*ql,*kh,*kl,*vth,*vtl,*ph,*pl,*ath,*atl,*oh,*ol;
    __nv_bfloat16 *wqh,*wql,*wkh,*wkl,*wvh,*wvl,*woh,*wol,*wlh,*wll;
    cudaGetSymbolAddress((void**)&s,    g_s);
    cudaGetSymbolAddress((void**)&wo,   g_wo);
    cudaGetSymbolAddress((void**)&o,    g_o);
    cudaGetSymbolAddress((void**)&lin,  g_lin);
    cudaGetSymbolAddress((void**)&tlnh, g_tln_h); cudaGetSymbolAddress((void**)&tlnl, g_tln_l);
    cudaGetSymbolAddress((void**)&vlnh, g_vln_h); cudaGetSymbolAddress((void**)&vlnl, g_vln_l);
    cudaGetSymbolAddress((void**)&qh,  g_q_h);  cudaGetSymbolAddress((void**)&ql,  g_q_l);
    cudaGetSymbolAddress((void**)&kh,  g_k_h);  cudaGetSymbolAddress((void**)&kl,  g_k_l);
    cudaGetSymbolAddress((void**)&vth, g_vt_h); cudaGetSymbolAddress((void**)&vtl, g_vt_l);
    cudaGetSymbolAddress((void**)&ph,  g_p_h);  cudaGetSymbolAddress((void**)&pl,  g_p_l);
    cudaGetSymbolAddress((void**)&ath, g_at_h); cudaGetSymbolAddress((void**)&atl, g_at_l);
    cudaGetSymbolAddress((void**)&oh,  g_o_h);  cudaGetSymbolAddress((void**)&ol,  g_o_l);
    cudaGetSymbolAddress((void**)&wqh, g_wq_h); cudaGetSymbolAddress((void**)&wql, g_wq_l);
    cudaGetSymbolAddress((void**)&wkh, g_wk_h); cudaGetSymbolAddress((void**)&wkl, g_wk_l);
    cudaGetSymbolAddress((void**)&wvh, g_wv_h); cudaGetSymbolAddress((void**)&wvl, g_wv_l);
    cudaGetSymbolAddress((void**)&woh, g_wo_h); cudaGetSymbolAddress((void**)&wol, g_wo_l);
    cudaGetSymbolAddress((void**)&wlh, g_wl_h); cudaGetSymbolAddress((void**)&wll, g_wl_l);

    cudaFuncSetAttribute(qkv_kernel,               cudaFuncAttributeMaxDynamicSharedMemorySize, SMEM_SZ);
    cudaFuncSetAttribute(mm_kernel<0,true,false>,  cudaFuncAttributeMaxDynamicSharedMemorySize, SMEM_SZ);
    cudaFuncSetAttribute(mm_kernel<0,false,true>,  cudaFuncAttributeMaxDynamicSharedMemorySize, SMEM_SZ);
    cudaFuncSetAttribute(mm_kernel<1,true,false>,  cudaFuncAttributeMaxDynamicSharedMemorySize, SMEM_SZ);

    // 0) all 5 weights -> bf16 hi/lo, ONE launch
    conv5_k<<<dim3(EMBED * EMBED / 512, 5), 256>>>(
        Wq, wqh, wql, Wk, wkh, wkl, Wv, wvh, wvl, Wo, woh, wol, Wl, wlh, wll);

    // 1) LN1 text + video, ONE launch
    ln1_k<<<NTXT + NVID, 256>>>(text, video, tlnh, tlnl, vlnh, vlnl, ln1_g, ln1_b);

    // 2) Q / K / Vt projections, ONE launch; grid = max over jobs, guarded per job
    qkv_kernel<<<dim3(NVID/BN, NTXT/BM, 3), 256, SMEM_SZ>>>(
        tlnh, tlnl, vlnh, vlnl, wqh, wql, wkh, wkl, wvh, wvl,
        bq, bk, bv, qh, ql, kh, kl, vth, vtl);

    // 3) logits S'[h][t][v] = (1/16) Q_h @ K_h^T  [4096x768], z = head
    mm_kernel<0,true,false><<<dim3(NVID/BN, NTXT/BM, HEADS), 256, SMEM_SZ>>>(
        qh, ql, EMBED, HDIM, kh, kl, EMBED, HDIM, nullptr,
        s, nullptr, nullptr, NVID, NTXT*NVID, HDIM, 1.f/16.f);

    // 4) softmax over 12 frames -> P hi/lo
    softmax_k<<<(HEADS * NTXT * VIDS) / 256, 256>>>(s, ph, pl);

    // 5) attn[t, h*256+d] = (1/64) P_h @ Vt_h^T [4096x256], z = head
    mm_kernel<0,false,true><<<dim3(HDIM/BN, NTXT/BM, HEADS), 256, SMEM_SZ>>>(
        ph, pl, NVID, NTXT*NVID, vth, vtl, NVID, HDIM*NVID, nullptr,
        nullptr, ath, atl, EMBED, HDIM, NVID, 1.f/64.f);

    // 6) Wo projection -> fp32, then LN2 (fp32 + bf16 hi/lo)
    mm_kernel<1,true,false><<<dim3(EMBED/BN, NTXT/BM, 1), 256, SMEM_SZ>>>(
        ath, atl, EMBED, 0, woh, wol, EMBED, 0, bo,
        wo, nullptr, nullptr, EMBED, 0, EMBED, 1.f);
    ln_k<true,true,false><<<NTXT, 256>>>(wo, nullptr, o, oh, ol, ln2_g, ln2_b);

    // 7) Wl linear -> fp32, then residual + LN3 -> out
    mm_kernel<1,true,false><<<dim3(EMBED/BN, NTXT/BM, 1), 256, SMEM_SZ>>>(
        oh, ol, EMBED, 0, wlh, wll, EMBED, 0, bl,
        lin, nullptr, nullptr, EMBED, 0, EMBED, 1.f);
    ln_k<true,false,true><<<NTXT, 256>>>(o, lin, out, nullptr, nullptr, ln3_g, ln3_b);
}

// round 11
// speedup vs baseline: 2.5757x; 1.1265x over previous
#include <cuda_runtime.h>
#include <cuda_bf16.h>
#include <math_constants.h>
#include <cstdint>

typedef unsigned long long u64;

#define EMBED  512
#define HEADS  2
#define HDIM   256
#define NTXT   4096
#define NVID   768
#define FRAMES 12
#define VIDS   64

#define BM 128
#define BN 128
#define BK 32
#define LDT 40                       // 32 + 8 pad bf16 -> 80B row stride (16B-mult, ldmatrix conflict-free)

static const int TILE_B  = 128 * LDT * 2;   // 10240 B per tile
static const int STAGE_B = 4 * TILE_B;      // Ah, Al, Bh, Bl
static const int SMEM_SZ = 2 * STAGE_B;     // 81920 B double-buffered (2 CTAs/SM = 160KB < 228KB)

// ---------------- device scratch ----------------
__device__ float g_s   [HEADS*(size_t)NTXT*NVID];   // logits S'[h][t][v]
__device__ float g_wo  [NTXT*EMBED];
__device__ float g_o   [NTXT*EMBED];
__device__ float g_lin [NTXT*EMBED];

__device__ __nv_bfloat16 g_tln_h[NTXT*EMBED],  g_tln_l[NTXT*EMBED];
__device__ __nv_bfloat16 g_vln_h[NVID*EMBED],  g_vln_l[NVID*EMBED];
__device__ __nv_bfloat16 g_q_h [NTXT*EMBED],   g_q_l [NTXT*EMBED];
__device__ __nv_bfloat16 g_k_h [NVID*EMBED],   g_k_l [NVID*EMBED];
__device__ __nv_bfloat16 g_vt_h[EMBED*NVID],   g_vt_l[EMBED*NVID];
__device__ __nv_bfloat16 g_p_h [HEADS*(size_t)NTXT*NVID], g_p_l[HEADS*(size_t)NTXT*NVID];
__device__ __nv_bfloat16 g_at_h[NTXT*EMBED],   g_at_l[NTXT*EMBED];
__device__ __nv_bfloat16 g_o_h [NTXT*EMBED],   g_o_l [NTXT*EMBED];
__device__ __nv_bfloat16 g_wq_h[EMBED*EMBED],  g_wq_l[EMBED*EMBED];
__device__ __nv_bfloat16 g_wk_h[EMBED*EMBED],  g_wk_l[EMBED*EMBED];
__device__ __nv_bfloat16 g_wv_h[EMBED*EMBED],  g_wv_l[EMBED*EMBED];
__device__ __nv_bfloat16 g_wo_h[EMBED*EMBED],  g_wo_l[EMBED*EMBED];
__device__ __nv_bfloat16 g_wl_h[EMBED*EMBED],  g_wl_l[EMBED*EMBED];

// ---------------- PTX helpers (all baseline sm_80+ instructions) ----------------
__device__ __forceinline__ uint32_t smem_u32(const void* p) {
    uint32_t a;
    asm("{ .reg .u64 t; cvta.to.shared.u64 t, %1; cvt.u32.u64 %0, t; }" : "=r"(a) : "l"(p));
    return a;
}
__device__ __forceinline__ void cpa16(uint32_t d, const void* g) {
    asm volatile("cp.async.cg.shared.global [%0], [%1], 16;" :: "r"(d), "l"(g));
}
__device__ __forceinline__ void ldsm4(uint32_t& r0, uint32_t& r1, uint32_t& r2, uint32_t& r3,
                                      uint32_t a) {
    asm volatile("ldmatrix.sync.aligned.m8n8.x4.shared.b16 {%0,%1,%2,%3}, [%4];"
                 : "=r"(r0), "=r"(r1), "=r"(r2), "=r"(r3) : "r"(a));
}
__device__ __forceinline__ void mma_bf16(float* c, const uint32_t* a, const uint32_t* b) {
    asm volatile("mma.sync.aligned.m16n8k16.row.col.f32.bf16.bf16.f32 "
                 "{%0,%1,%2,%3}, {%4,%5,%6,%7}, {%8,%9}, {%0,%1,%2,%3};"
                 : "+f"(c[0]), "+f"(c[1]), "+f"(c[2]), "+f"(c[3])
                 : "r"(a[0]), "r"(a[1]), "r"(a[2]), "r"(a[3]), "r"(b[0]), "r"(b[1]));
}
__device__ __forceinline__ void split_bf16(float v, __nv_bfloat16& h, __nv_bfloat16& l) {
    h = __float2bfloat16(v);
    l = __float2bfloat16(v - __bfloat162float(h));
}

// ============================================================
// HMMA NT GEMM core. C = alpha*(Ah+Al).(Bh+Bl)^T (+bias), 3-term bf16 split.
// 128x128x32 tiles, 256 thr, warp-tile 32x64.
// R11: B fragments processed in two n-halves to cut live registers
// (fragments 48 -> 32) so 2 CTAs/SM fit (reg target 128).
// BIASM: 0 none, 1 per-n, 2 per-m.  WF32/WB16: output formats.
// ============================================================
template<int BIASM, bool WF32, bool WB16>
__device__ __forceinline__ void mm_core(
    const __nv_bfloat16* __restrict__ Ah, const __nv_bfloat16* __restrict__ Al, int lda,
    const __nv_bfloat16* __restrict__ Bh, const __nv_bfloat16* __restrict__ Bl, int ldb,
    const float* __restrict__ bias,
    float* __restrict__ Cf, __nv_bfloat16* __restrict__ Ch, __nv_bfloat16* __restrict__ Cl,
    int ldc, int K, float alpha, int m0, int n0, char* smem)
{
    const uint32_t sb = smem_u32(smem);
    const int tid = threadIdx.x, wid = tid >> 5, lane = tid & 31;

    const int mw = (wid & 3) * 32;       // warp m offset in tile
    const int nw = (wid >> 2) * 64;      // warp n offset in tile

    const int lr = tid >> 2;             // 0..63 row
    const int lc = (tid & 3) * 8;        // bf16 col: 0,8,16,24

    auto load_stage = [&](int s, int buf) {
        const int kb = s * BK;
#pragma unroll
        for (int t = 0; t < 4; t++) {
            const __nv_bfloat16* sp = (t == 0) ? Ah : (t == 1) ? Al : (t == 2) ? Bh : Bl;
            const int r0g = (t < 2) ? m0 : n0;
            const int ld  = (t < 2) ? lda : ldb;
            const uint32_t db = sb + buf * STAGE_B + t * TILE_B;
#pragma unroll
            for (int p = 0; p < 2; p++) {
                const int r = lr + p * 64;
                cpa16(db + (r * LDT + lc) * 2,
                      sp + (size_t)(r0g + r) * ld + kb + lc);
            }
        }
        asm volatile("cp.async.commit_group;" ::: "memory");
    };

    float acc[2][8][4];
#pragma unroll
    for (int i = 0; i < 2; i++)
#pragma unroll
        for (int j = 0; j < 8; j++)
#pragma unroll
            for (int r = 0; r < 4; r++) acc[i][j][r] = 0.f;

    const int row_a = lane & 15;
    const int ka    = (lane >> 4) * 8;
    const int row_b = (lane & 7) + ((lane & 16) >> 1);
    const int kb_   = lane & 8;

    const int S = K / BK;
    int buf = 0;
    load_stage(0, 0);

    for (int s = 0; s < S; s++) {
        if (s + 1 < S) {
            load_stage(s + 1, buf ^ 1);
            asm volatile("cp.async.wait_group 1;" ::: "memory");
        } else {
            asm volatile("cp.async.wait_group 0;" ::: "memory");
        }
        __syncthreads();

        const uint32_t abh = sb + buf * STAGE_B;
        const uint32_t abl = abh + TILE_B;
        const uint32_t bbh = abh + 2 * TILE_B;
        const uint32_t bbl = abh + 3 * TILE_B;

#pragma unroll
        for (int kk = 0; kk < 2; kk++) {
            const int k0 = kk * 16;
            uint32_t ah[2][4], al_[2][4];
#pragma unroll
            for (int mf = 0; mf < 2; mf++) {
                const uint32_t off = ((mw + mf * 16 + row_a) * LDT + k0 + ka) * 2;
                ldsm4(ah[mf][0], ah[mf][1], ah[mf][2], ah[mf][3], abh + off);
                ldsm4(al_[mf][0], al_[mf][1], al_[mf][2], al_[mf][3], abl + off);
            }
            // process B in two 32-wide n-halves: only 4+4 B fragments live at once
#pragma unroll
            for (int h2 = 0; h2 < 2; h2++) {
                uint32_t bh[4][2], bl_[4][2];
#pragma unroll
                for (int p = 0; p < 2; p++) {
                    const int pp = h2 * 2 + p;
                    const uint32_t off = ((nw + pp * 16 + row_b) * LDT + k0 + kb_) * 2;
                    ldsm4(bh[2*p][0], bh[2*p][1], bh[2*p+1][0], bh[2*p+1][1], bbh + off);
                    ldsm4(bl_[2*p][0], bl_[2*p][1], bl_[2*p+1][0], bl_[2*p+1][1], bbl + off);
                }
#pragma unroll
                for (int mf = 0; mf < 2; mf++)
#pragma unroll
                    for (int nf = 0; nf < 4; nf++) {
                        float* a4 = acc[mf][h2 * 4 + nf];
                        mma_bf16(a4, ah[mf],  bh[nf]);
                        mma_bf16(a4, ah[mf],  bl_[nf]);
                        mma_bf16(a4, al_[mf], bh[nf]);
                    }
            }
        }
        __syncthreads();
        buf ^= 1;
    }

    // ---- epilogue ----
    const int er = lane >> 2, ec = (lane & 3) * 2;
#pragma unroll
    for (int mf = 0; mf < 2; mf++) {
#pragma unroll
        for (int rh = 0; rh < 2; rh++) {
            const int m = m0 + mw + mf * 16 + er + rh * 8;
            const float bm = (BIASM == 2) ? __ldg(bias + m) : 0.f;
#pragma unroll
            for (int nf = 0; nf < 8; nf++) {
                const int n = n0 + nw + nf * 8 + ec;
                float v0 = acc[mf][nf][rh * 2]     * alpha;
                float v1 = acc[mf][nf][rh * 2 + 1] * alpha;
                if (BIASM == 1) { v0 += __ldg(bias + n); v1 += __ldg(bias + n + 1); }
                if (BIASM == 2) { v0 += bm; v1 += bm; }
                if (WF32)
                    *(float2*)(Cf + (size_t)m * ldc + n) = make_float2(v0, v1);
                if (WB16) {
                    __nv_bfloat16 h0, l0, h1, l1;
                    split_bf16(v0, h0, l0);
                    split_bf16(v1, h1, l1);
                    __nv_bfloat162 hh(h0, h1), ll(l0, l1);
                    *(uint32_t*)(Ch + (size_t)m * ldc + n) = *(uint32_t*)&hh;
                    *(uint32_t*)(Cl + (size_t)m * ldc + n) = *(uint32_t*)&ll;
                }
            }
        }
    }
}

// ---- GEMM kernel wrappers (min 2 blocks/SM -> reg target 128) ----
template<int BIASM, bool WF32, bool WB16>
__global__ __launch_bounds__(256, 2) void mm_kernel(
    const __nv_bfloat16* __restrict__ Ah, const __nv_bfloat16* __restrict__ Al,
    int lda, int zsA,
    const __nv_bfloat16* __restrict__ Bh, const __nv_bfloat16* __restrict__ Bl,
    int ldb, int zsB,
    const float* __restrict__ bias,
    float* __restrict__ Cf, __nv_bfloat16* __restrict__ Ch, __nv_bfloat16* __restrict__ Cl,
    int ldc, int zsC,
    int K, float alpha)
{
    extern __shared__ char smem[];
    const int z = blockIdx.z;
    Ah += (size_t)z * zsA;  Al += (size_t)z * zsA;
    Bh += (size_t)z * zsB;  Bl += (size_t)z * zsB;
    if (WF32) Cf += (size_t)z * zsC;
    if (WB16) { Ch += (size_t)z * zsC; Cl += (size_t)z * zsC; }
    mm_core<BIASM, WF32, WB16>(Ah, Al, lda, Bh, Bl, ldb, bias, Cf, Ch, Cl,
                               ldc, K, alpha, blockIdx.y * BM, blockIdx.x * BN, smem);
}

// fused Q / K / Vt projections in one launch (z = 0:Q, 1:K, 2:Vt)
//   Q : [4096 x 512], K=512 -> x<4,  y<32
//   K : [ 768 x 512], K=512 -> x<4,  y<6
//   Vt: [ 512 x 768], K=512 -> x<6,  y<4
__global__ __launch_bounds__(256, 2) void qkv_kernel(
    const __nv_bfloat16* __restrict__ tlnh, const __nv_bfloat16* __restrict__ tlnl,
    const __nv_bfloat16* __restrict__ vlnh, const __nv_bfloat16* __restrict__ vlnl,
    const __nv_bfloat16* __restrict__ wqh,  const __nv_bfloat16* __restrict__ wql,
    const __nv_bfloat16* __restrict__ wkh,  const __nv_bfloat16* __restrict__ wkl,
    const __nv_bfloat16* __restrict__ wvh,  const __nv_bfloat16* __restrict__ wvl,
    const float* __restrict__ bq, const float* __restrict__ bk, const float* __restrict__ bv,
    __nv_bfloat16* __restrict__ qh,  __nv_bfloat16* __restrict__ ql,
    __nv_bfloat16* __restrict__ kh,  __nv_bfloat16* __restrict__ kl,
    __nv_bfloat16* __restrict__ vth, __nv_bfloat16* __restrict__ vtl)
{
    extern __shared__ char smem[];
    const int z = blockIdx.z;
    const int bx = blockIdx.x, by = blockIdx.y;
    const int m0 = by * BM, n0 = bx * BN;
    if (z == 0) {
        if (bx >= EMBED / BN || by >= NTXT / BM) return;
        mm_core<1,false,true>(tlnh, tlnl, EMBED, wqh, wql, EMBED, bq,
                              nullptr, qh, ql, EMBED, EMBED, 1.f, m0, n0, smem);
    } else if (z == 1) {
        if (bx >= EMBED / BN || by >= NVID / BM) return;
        mm_core<1,false,true>(vlnh, vlnl, EMBED, wkh, wkl, EMBED, bk,
                              nullptr, kh, kl, EMBED, EMBED, 1.f, m0, n0, smem);
    } else {
        if (bx >= NVID / BN || by >= EMBED / BM) return;
        // Vt[d, vm] = Wv @ vln^T + bv (per-m bias), ldc = NVID, contraction K = EMBED
        mm_core<2,false,true>(wvh, wvl, EMBED, vlnh, vlnl, EMBED, bv,
                              nullptr, vth, vtl, NVID, EMBED, 1.f, m0, n0, smem);
    }
}

// ============================================================
// LayerNorm (rows of 512). Optional residual x2; fp32 / bf16-hi/lo outputs.
// ============================================================
template<bool W32, bool W16, bool HAS2>
__device__ __forceinline__ void ln_core(
    const float* __restrict__ x, const float* __restrict__ x2,
    float* __restrict__ yf, __nv_bfloat16* __restrict__ yh, __nv_bfloat16* __restrict__ yl,
    const float* __restrict__ g, const float* __restrict__ b, int row)
{
    int t = threadIdx.x;
    float2 v = ((const float2*)(x + (size_t)row * EMBED))[t];
    if (HAS2) {
        float2 w = ((const float2*)(x2 + (size_t)row * EMBED))[t];
        v.x += w.x; v.y += w.y;
    }
    float s = v.x + v.y, s2 = v.x * v.x + v.y * v.y;
#pragma unroll
    for (int o = 16; o; o >>= 1) {
        s  += __shfl_xor_sync(0xffffffffu, s,  o);
        s2 += __shfl_xor_sync(0xffffffffu, s2, o);
    }
    __shared__ float rs[8], rs2[8];
    if ((t & 31) == 0) { rs[t >> 5] = s; rs2[t >> 5] = s2; }
    __syncthreads();
    if (t < 32) {
        float a  = t < 8 ? rs[t]  : 0.f;
        float a2 = t < 8 ? rs2[t] : 0.f;
#pragma unroll
        for (int o = 4; o; o >>= 1) {
            a  += __shfl_xor_sync(0xffffffffu, a,  o);
            a2 += __shfl_xor_sync(0xffffffffu, a2, o);
        }
        if (t == 0) { rs[0] = a; rs2[0] = a2; }
    }
    __syncthreads();
    float mu  = rs[0]  * (1.f / EMBED);
    float var = rs2[0] * (1.f / EMBED) - mu * mu;
    float inv = rsqrtf(var + 1e-5f);
    float2 gg = ((const float2*)g)[t], bb = ((const float2*)b)[t];
    float2 r = make_float2((v.x - mu) * inv * gg.x + bb.x,
                           (v.y - mu) * inv * gg.y + bb.y);
    if (W32) ((float2*)(yf + (size_t)row * EMBED))[t] = r;
    if (W16) {
        __nv_bfloat16 h0, l0, h1, l1;
        split_bf16(r.x, h0, l0);
        split_bf16(r.y, h1, l1);
        __nv_bfloat162 hh(h0, h1), ll(l0, l1);
        ((uint32_t*)(yh + (size_t)row * EMBED))[t] = *(uint32_t*)&hh;
        ((uint32_t*)(yl + (size_t)row * EMBED))[t] = *(uint32_t*)&ll;
    }
}

template<bool W32, bool W16, bool HAS2>
__global__ __launch_bounds__(256) void ln_k(
    const float* __restrict__ x, const float* __restrict__ x2,
    float* __restrict__ yf, __nv_bfloat16* __restrict__ yh, __nv_bfloat16* __restrict__ yl,
    const float* __restrict__ g, const float* __restrict__ b)
{
    ln_core<W32, W16, HAS2>(x, x2, yf, yh, yl, g, b, blockIdx.x);
}

// fused LN1 over text (rows 0..4095) + video (rows 4096..4863)
__global__ __launch_bounds__(256) void ln1_k(
    const float* __restrict__ text, const float* __restrict__ video,
    __nv_bfloat16* __restrict__ tlnh, __nv_bfloat16* __restrict__ tlnl,
    __nv_bfloat16* __restrict__ vlnh, __nv_bfloat16* __restrict__ vlnl,
    const float* __restrict__ g, const float* __restrict__ b)
{
    int row = blockIdx.x;
    if (row < NTXT)
        ln_core<false,true,false>(text, nullptr, nullptr, tlnh, tlnl, g, b, row);
    else
        ln_core<false,true,false>(video, nullptr, nullptr, vlnh, vlnl, g, b, row - NTXT);
}

// ============================================================
// Softmax over 12 contiguous frames: S'[h][t][a*12+f] -> P hi/lo bf16.
// ============================================================
__global__ __launch_bounds__(256) void softmax_k(
    const float* __restrict__ S, __nv_bfloat16* __restrict__ Ph, __nv_bfloat16* __restrict__ Pl)
{
    int idx = blockIdx.x * 256 + threadIdx.x;          // ((h*4096+t)*64 + a)
    size_t off = (size_t)(idx >> 6) * NVID + (idx & 63) * FRAMES;
    const float* base = S + off;
    float4 v0 = *(const float4*)(base);
    float4 v1 = *(const float4*)(base + 4);
    float4 v2 = *(const float4*)(base + 8);
    float vl[12] = {v0.x,v0.y,v0.z,v0.w, v1.x,v1.y,v1.z,v1.w, v2.x,v2.y,v2.z,v2.w};
    float m = -CUDART_INF_F;
#pragma unroll
    for (int f = 0; f < 12; f++) m = fmaxf(m, vl[f]);
    float sum = 0.f;
#pragma unroll
    for (int f = 0; f < 12; f++) { vl[f] = __expf(vl[f] - m); sum += vl[f]; }
    float inv = 1.f / sum;
    uint32_t hp[6], lp[6];
#pragma unroll
    for (int g = 0; g < 6; g++) {
        __nv_bfloat16 h0, l0, h1, l1;
        split_bf16(vl[2*g]   * inv, h0, l0);
        split_bf16(vl[2*g+1] * inv, h1, l1);
        __nv_bfloat162 hh(h0, h1), ll(l0, l1);
        hp[g] = *(uint32_t*)&hh;  lp[g] = *(uint32_t*)&ll;
    }
#pragma unroll
    for (int g = 0; g < 3; g++) {
        *(uint2*)(Ph + off + g * 4) = make_uint2(hp[2*g], hp[2*g+1]);
        *(uint2*)(Pl + off + g * 4) = make_uint2(lp[2*g], lp[2*g+1]);
    }
}

// fused fp32 -> bf16 hi/lo converter for ALL 5 weights (grid.y selects weight)
__global__ __launch_bounds__(256) void conv5_k(
    const float* __restrict__ s0, __nv_bfloat16* __restrict__ h0, __nv_bfloat16* __restrict__ l0,
    const float* __restrict__ s1, __nv_bfloat16* __restrict__ h1, __nv_bfloat16* __restrict__ l1,
    const float* __restrict__ s2, __nv_bfloat16* __restrict__ h2, __nv_bfloat16* __restrict__ l2,
    const float* __restrict__ s3, __nv_bfloat16* __restrict__ h3, __nv_bfloat16* __restrict__ l3,
    const float* __restrict__ s4, __nv_bfloat16* __restrict__ h4, __nv_bfloat16* __restrict__ l4)
{
    const float* s; __nv_bfloat16 *h, *l;
    switch (blockIdx.y) {
        case 0: s = s0; h = h0; l = l0; break;
        case 1: s = s1; h = h1; l = l1; break;
        case 2: s = s2; h = h2; l = l2; break;
        case 3: s = s3; h = h3; l = l3; break;
        default: s = s4; h = h4; l = l4; break;
    }
    int i = (blockIdx.x * 256 + threadIdx.x) * 2;
    float2 v = *(const float2*)(s + i);
    __nv_bfloat16 ha, la, hb, lb;
    split_bf16(v.x, ha, la);
    split_bf16(v.y, hb, lb);
    __nv_bfloat162 hh(ha, hb), ll(la, lb);
    *(uint32_t*)(h + i) = *(uint32_t*)&hh;
    *(uint32_t*)(l + i) = *(uint32_t*)&ll;
}

// ============================================================
extern "C" void kernel_launch(void* const* d_in, const int* in_sizes, int n_in,
                              void* d_out, int out_size)
{
    const float* text  = (const float*)d_in[0];
    const float* video = (const float*)d_in[1];
    const float* ln1_g = (const float*)d_in[2];
    const float* ln1_b = (const float*)d_in[3];
    const float* Wq    = (const float*)d_in[4];
    const float* bq    = (const float*)d_in[5];
    const float* Wk    = (const float*)d_in[6];
    const float* bk    = (const float*)d_in[7];
    const float* Wv    = (const float*)d_in[8];
    const float* bv    = (const float*)d_in[9];
    const float* Wo    = (const float*)d_in[10];
    const float* bo    = (const float*)d_in[11];
    const float* Wl    = (const float*)d_in[12];
    const float* bl    = (const float*)d_in[13];
    const float* ln2_g = (const float*)d_in[14];
    const float* ln2_b = (const float*)d_in[15];
    const float* ln3_g = (const float*)d_in[16];
    const float* ln3_b = (const float*)d_in[17];
    float* out = (float*)d_out;

    float *s, *wo, *o, *lin;
    __nv_bfloat16 *tlnh,*tlnl,*vlnh,*vlnl,*qh,*ql,*kh,*kl,*vth,*vtl,*ph,*pl,*ath,*atl,*oh,*ol;
    __nv_bfloat16 *wqh,*wql,*wkh,*wkl,*wvh,*wvl,*woh,*wol,*wlh,*wll;
    cudaGetSymbolAddress((void**)&s,    g_s);
    cudaGetSymbolAddress((void**)&wo,   g_wo);
    cudaGetSymbolAddress((void**)&o,    g_o);
    cudaGetSymbolAddress((void**)&lin,  g_lin);
    cudaGetSymbolAddress((void**)&tlnh, g_tln_h); cudaGetSymbolAddress((void**)&tlnl, g_tln_l);
    cudaGetSymbolAddress((void**)&vlnh, g_vln_h); cudaGetSymbolAddress((void**)&vlnl, g_vln_l);
    cudaGetSymbolAddress((void**)&qh,  g_q_h);  cudaGetSymbolAddress((void**)&ql,  g_q_l);
    cudaGetSymbolAddress((void**)&kh,  g_k_h);  cudaGetSymbolAddress((void**)&kl,  g_k_l);
    cudaGetSymbolAddress((void**)&vth, g_vt_h); cudaGetSymbolAddress((void**)&vtl, g_vt_l);
    cudaGetSymbolAddress((void**)&ph,  g_p_h);  cudaGetSymbolAddress((void**)&pl,  g_p_l);
    cudaGetSymbolAddress((void**)&ath, g_at_h); cudaGetSymbolAddress((void**)&atl, g_at_l);
    cudaGetSymbolAddress((void**)&oh,  g_o_h);  cudaGetSymbolAddress((void**)&ol,  g_o_l);
    cudaGetSymbolAddress((void**)&wqh, g_wq_h); cudaGetSymbolAddress((void**)&wql, g_wq_l);
    cudaGetSymbolAddress((void**)&wkh, g_wk_h); cudaGetSymbolAddress((void**)&wkl, g_wk_l);
    cudaGetSymbolAddress((void**)&wvh, g_wv_h); cudaGetSymbolAddress((void**)&wvl, g_wv_l);
    cudaGetSymbolAddress((void**)&woh, g_wo_h); cudaGetSymbolAddress((void**)&wol, g_wo_l);
    cudaGetSymbolAddress((void**)&wlh, g_wl_h); cudaGetSymbolAddress((void**)&wll, g_wl_l);

    cudaFuncSetAttribute(qkv_kernel,               cudaFuncAttributeMaxDynamicSharedMemorySize, SMEM_SZ);
    cudaFuncSetAttribute(mm_kernel<0,true,false>,  cudaFuncAttributeMaxDynamicSharedMemorySize, SMEM_SZ);
    cudaFuncSetAttribute(mm_kernel<0,false,true>,  cudaFuncAttributeMaxDynamicSharedMemorySize, SMEM_SZ);
    cudaFuncSetAttribute(mm_kernel<1,true,false>,  cudaFuncAttributeMaxDynamicSharedMemorySize, SMEM_SZ);

    // 0) all 5 weights -> bf16 hi/lo, ONE launch
    conv5_k<<<dim3(EMBED * EMBED / 512, 5), 256>>>(
        Wq, wqh, wql, Wk, wkh, wkl, Wv, wvh, wvl, Wo, woh, wol, Wl, wlh, wll);

    // 1) LN1 text + video, ONE launch
    ln1_k<<<NTXT + NVID, 256>>>(text, video, tlnh, tlnl, vlnh, vlnl, ln1_g, ln1_b);

    // 2) Q / K / Vt projections, ONE launch; grid = max over jobs, guarded per job
    qkv_kernel<<<dim3(NVID/BN, NTXT/BM, 3), 256, SMEM_SZ>>>(
        tlnh, tlnl, vlnh, vlnl, wqh, wql, wkh, wkl, wvh, wvl,
        bq, bk, bv, qh, ql, kh, kl, vth, vtl);

    // 3) logits S'[h][t][v] = (1/16) Q_h @ K_h^T  [4096x768], z = head
    mm_kernel<0,true,false><<<dim3(NVID/BN, NTXT/BM, HEADS), 256, SMEM_SZ>>>(
        qh, ql, EMBED, HDIM, kh, kl, EMBED, HDIM, nullptr,
        s, nullptr, nullptr, NVID, NTXT*NVID, HDIM, 1.f/16.f);

    // 4) softmax over 12 frames -> P hi/lo
    softmax_k<<<(HEADS * NTXT * VIDS) / 256, 256>>>(s, ph, pl);

    // 5) attn[t, h*256+d] = (1/64) P_h @ Vt_h^T [4096x256], z = head
    mm_kernel<0,false,true><<<dim3(HDIM/BN, NTXT/BM, HEADS), 256, SMEM_SZ>>>(
        ph, pl, NVID, NTXT*NVID, vth, vtl, NVID, HDIM*NVID, nullptr,
        nullptr, ath, atl, EMBED, HDIM, NVID, 1.f/64.f);

    // 6) Wo projection -> fp32, then LN2 (fp32 + bf16 hi/lo)
    mm_kernel<1,true,false><<<dim3(EMBED/BN, NTXT/BM, 1), 256, SMEM_SZ>>>(
        ath, atl, EMBED, 0, woh, wol, EMBED, 0, bo,
        wo, nullptr, nullptr, EMBED, 0, EMBED, 1.f);
    ln_k<true,true,false><<<NTXT, 256>>>(wo, nullptr, o, oh, ol, ln2_g, ln2_b);

    // 7) Wl linear -> fp32, then residual + LN3 -> out
    mm_kernel<1,true,false><<<dim3(EMBED/BN, NTXT/BM, 1), 256, SMEM_SZ>>>(
        oh, ol, EMBED, 0, wlh, wll, EMBED, 0, bl,
        lin, nullptr, nullptr, EMBED, 0, EMBED, 1.f);
    ln_k<true,false,true><<<NTXT, 256>>>(o, lin, out, nullptr, nullptr, ln3_g, ln3_b);
}